// round 14
// baseline (speedup 1.0000x reference)
#include <cuda_runtime.h>
#include <math.h>

#define D       128
#define NN      50000
#define NE      600000
#define EPS_BN  1e-5f
#define EPS_ETA 1e-6f
#define NBLK    148
#define NTHR    1024
#define NWARP   32
#define CHUNK   338          // ceil(NN / NBLK)

// ---------------- device-global scratch (no allocations allowed) -------------
__device__ float g_wT[8 * D * D];     // transposed weights: [k*D + c]
__device__ float g_b1h[NN * D];
__device__ float g_b2h[NN * D];
__device__ float g_a1h[NN * D];
__device__ float g_v[NN * D];
__device__ float g_c1p[NN * D];
__device__ float g_c2p[NN * D];
__device__ float g_agg_h[NN * D];     // h_new
__device__ int2  g_rec[NE];           // (src, eid) in dst-sorted (CSR) order
__device__ float g_stats[4 * D];      // e_sum, e_sq, h_sum, h_sq
__device__ int   g_deg[NN];
__device__ int   g_start[NN];
__device__ int   g_cursor[NN];
__device__ int   g_remain[NN];
__device__ int   g_gbase = 0;
__device__ int   g_ctr1 = 0;          // work-steal counters
__device__ int   g_ctr4 = 0;
__device__ int            g_bar_count = 0;
__device__ volatile int   g_bar_gen   = 0;

__device__ __forceinline__ float sigf(float x) {
    return __fdividef(1.0f, 1.0f + __expf(-x));
}

// ---------------- software grid barrier (all NBLK blocks co-resident) --------
__device__ __forceinline__ void grid_barrier()
{
    __syncthreads();
    if (threadIdx.x == 0) {
        int gen = g_bar_gen;
        __threadfence();
        if (atomicAdd(&g_bar_count, 1) == NBLK - 1) {
            g_bar_count = 0;
            __threadfence();
            g_bar_gen = gen + 1;
        } else {
            while (g_bar_gen == gen) { __nanosleep(64); }
        }
        __threadfence();
    }
    __syncthreads();
}

// ---------------- packed f32x2 helpers (sm_103a) -------------------------------
__device__ __forceinline__ unsigned long long pk2(float a, float b) {
    unsigned long long r;
    asm("mov.b64 %0, {%1, %2};" : "=l"(r) : "f"(a), "f"(b));
    return r;
}
__device__ __forceinline__ float2 upk2(unsigned long long v) {
    float2 r;
    asm("mov.b64 {%0, %1}, %2;" : "=f"(r.x), "=f"(r.y) : "l"(v));
    return r;
}
__device__ __forceinline__ unsigned long long ffma2(
    unsigned long long a, unsigned long long b, unsigned long long c) {
    unsigned long long d;
    asm("fma.rn.f32x2 %0, %1, %2, %3;" : "=l"(d) : "l"(a), "l"(b), "l"(c));
    return d;
}

// ---------------- sync-free warp GEMM: 8 rows x 128 cols, K=128 ----------------
__device__ __forceinline__ void warp_gemm8(
    const float* __restrict__ Xr,
    const float* __restrict__ wT,
    int c0, unsigned long long acc[8][2])
{
    for (int k = 0; k < D; k += 4) {
        ulonglong2 w0 = *(const ulonglong2*)(wT + (size_t)(k + 0) * D + c0);
        ulonglong2 w1 = *(const ulonglong2*)(wT + (size_t)(k + 1) * D + c0);
        ulonglong2 w2 = *(const ulonglong2*)(wT + (size_t)(k + 2) * D + c0);
        ulonglong2 w3 = *(const ulonglong2*)(wT + (size_t)(k + 3) * D + c0);
#pragma unroll
        for (int j = 0; j < 8; j++) {
            float4 xv = *(const float4*)(Xr + (size_t)j * D + k);
            unsigned long long b;
            b = pk2(xv.x, xv.x);
            acc[j][0] = ffma2(b, w0.x, acc[j][0]);
            acc[j][1] = ffma2(b, w0.y, acc[j][1]);
            b = pk2(xv.y, xv.y);
            acc[j][0] = ffma2(b, w1.x, acc[j][0]);
            acc[j][1] = ffma2(b, w1.y, acc[j][1]);
            b = pk2(xv.z, xv.z);
            acc[j][0] = ffma2(b, w2.x, acc[j][0]);
            acc[j][1] = ffma2(b, w2.y, acc[j][1]);
            b = pk2(xv.w, xv.w);
            acc[j][0] = ffma2(b, w3.x, acc[j][0]);
            acc[j][1] = ffma2(b, w3.y, acc[j][1]);
        }
    }
}

// ---------------- per-node aggregation + finalize (warp-cooperative) ----------
// Reads this node's CSR records + complete hat rows; writes h_new, p_out;
// accumulates h-stats into hs/hq.
__device__ __forceinline__ void agg_node(
    int n, int c0, int lane,
    const float* __restrict__ ehat, const float* __restrict__ p,
    float* __restrict__ p_out, float4& hs, float4& hq)
{
    const unsigned FULL = 0xFFFFFFFFu;
    int st = g_start[n];
    int dg = g_deg[n];
    float4 ss = make_float4(0.f, 0.f, 0.f, 0.f);
    float4 ah = make_float4(0.f, 0.f, 0.f, 0.f);
    float4 ap = make_float4(0.f, 0.f, 0.f, 0.f);

    int done = 0;
    while (done < dg) {
        int m = dg - done; if (m > 32) m = 32;
        int2 rr = make_int2(0, 0);
        if (lane < m) rr = g_rec[st + done + lane];
        for (int j = 0; j < m; j++) {
            int sa = __shfl_sync(FULL, rr.x, j);
            int ea = __shfl_sync(FULL, rr.y, j);
            const float4 hv = *(const float4*)(ehat + (size_t)ea * D + c0);
            const float4 vv = *(const float4*)(g_v + (size_t)sa * D + c0);
            const float4 cp = *(const float4*)(g_c2p + (size_t)sa * D + c0);
            float s0 = sigf(hv.x), s1 = sigf(hv.y), s2 = sigf(hv.z), s3 = sigf(hv.w);
            ss.x += s0; ss.y += s1; ss.z += s2; ss.w += s3;
            ah.x = fmaf(s0, vv.x, ah.x);
            ah.y = fmaf(s1, vv.y, ah.y);
            ah.z = fmaf(s2, vv.z, ah.z);
            ah.w = fmaf(s3, vv.w, ah.w);
            ap.x = fmaf(s0, cp.x, ap.x);
            ap.y = fmaf(s1, cp.y, ap.y);
            ap.z = fmaf(s2, cp.z, ap.z);
            ap.w = fmaf(s3, cp.w, ap.w);
        }
        done += m;
    }
    float i0 = __fdividef(1.0f, ss.x + EPS_ETA);
    float i1 = __fdividef(1.0f, ss.y + EPS_ETA);
    float i2 = __fdividef(1.0f, ss.z + EPS_ETA);
    float i3 = __fdividef(1.0f, ss.w + EPS_ETA);

    size_t off = (size_t)n * D + c0;
    float4 a1v = *(const float4*)(g_a1h + off);
    float4 hn = make_float4(fmaf(ah.x, i0, a1v.x), fmaf(ah.y, i1, a1v.y),
                            fmaf(ah.z, i2, a1v.z), fmaf(ah.w, i3, a1v.w));
    *(float4*)(g_agg_h + off) = hn;
    hs.x += hn.x; hq.x += hn.x * hn.x;
    hs.y += hn.y; hq.y += hn.y * hn.y;
    hs.z += hn.z; hq.z += hn.z * hn.z;
    hs.w += hn.w; hq.w += hn.w * hn.w;

    float4 c1 = *(const float4*)(g_c1p + off);
    float4 pv = *(const float4*)(p + off);
    float4 po;
    po.x = pv.x + tanhf(fmaf(ap.x, i0, c1.x));
    po.y = pv.y + tanhf(fmaf(ap.y, i1, c1.y));
    po.z = pv.z + tanhf(fmaf(ap.z, i2, c1.z));
    po.w = pv.w + tanhf(fmaf(ap.w, i3, c1.w));
    *(float4*)(p_out + off) = po;
}

// =============================================================================
// Single fused persistent kernel. grid = 148 x 1024.
// =============================================================================
__global__ void __launch_bounds__(NTHR) fused_gcn(
    const float* __restrict__ h, const float* __restrict__ e, const float* __restrict__ p,
    const int* __restrict__ src, const int* __restrict__ dst,
    const float* __restrict__ A1w, const float* __restrict__ A1b,
    const float* __restrict__ A2w, const float* __restrict__ A2b,
    const float* __restrict__ B1w, const float* __restrict__ B1b,
    const float* __restrict__ B2w, const float* __restrict__ B2b,
    const float* __restrict__ B3w, const float* __restrict__ B3b,
    const float* __restrict__ C1w, const float* __restrict__ C1b,
    const float* __restrict__ C2w, const float* __restrict__ C2b,
    const float* __restrict__ bn_h_g, const float* __restrict__ bn_h_b,
    const float* __restrict__ bn_e_g, const float* __restrict__ bn_e_b,
    float* __restrict__ h_out, float* __restrict__ ehat, float* __restrict__ p_out)
{
    __shared__ int   s_scan[512];
    __shared__ int   s_scan2[512];
    __shared__ float sA[D];
    __shared__ float sB[D];
    __shared__ float sC[D];
    __shared__ float sD[D];
    __shared__ float s_ss[4 * D];
    __shared__ int   s_off;

    const int tid  = threadIdx.x;
    const int lane = tid & 31;
    const int warp = tid >> 5;
    const int bid  = blockIdx.x;
    const int c0   = lane * 4;
    const int gtid = bid * NTHR + tid;
    const int gstr = NBLK * NTHR;          // 151552
    const int gw   = bid * NWARP + warp;
    const int NW   = NBLK * NWARP;         // 4736
    const unsigned FULL = 0xFFFFFFFFu;

    // ---------------- Ph0: zero deg/stats/counters + weight transpose ---------
    for (int i = gtid; i < NN; i += gstr) g_deg[i] = 0;
    if (gtid < 4 * D) g_stats[gtid] = 0.f;
    if (gtid == 0) { g_gbase = 0; g_ctr1 = 0; g_ctr4 = 0; }
    for (int i = gtid; i < 8 * D * D; i += gstr) {
        int j   = i >> 14;
        int rem = i & 16383;
        int k   = rem >> 7;
        int c   = rem & 127;
        float v;
        if      (j == 0) v = B1w[c * D + k];
        else if (j == 1) v = B2w[c * D + k];
        else if (j == 2) v = A1w[c * D + k];
        else if (j == 3) v = C1w[c * D + k];
        else if (j == 4) v = C2w[c * D + k];
        else if (j == 5) v = A2w[c * 2 * D + k];
        else if (j == 6) v = A2w[c * 2 * D + D + k];
        else             v = B3w[c * D + k];
        g_wT[i] = v;
    }
    grid_barrier();

    // ---------------- Ph1: dst histogram + node GEMMs (work-stealing) ---------
    for (int ei = gtid; ei < NE; ei += gstr) atomicAdd(&g_deg[dst[ei]], 1);
    {
        const int NSTRIP = NN / 8;     // 6250
        const int NJOB   = 6 * NSTRIP;
        int job = 0;
        if (lane == 0) job = atomicAdd(&g_ctr1, 1);
        job = __shfl_sync(FULL, job, 0);
        while (job < NJOB) {
            int next = 0;
            if (lane == 0) next = atomicAdd(&g_ctr1, 1);

            int jid   = job / NSTRIP;
            int strip = job - jid * NSTRIP;
            int row0  = strip * 8;
            unsigned long long acc[8][2];
#pragma unroll
            for (int j = 0; j < 8; j++) { acc[j][0] = 0ull; acc[j][1] = 0ull; }

            const float* bias;
            float* outp;
            if (jid == 0) {
                warp_gemm8(h + (size_t)row0 * D, g_wT + 0 * D * D, c0, acc);
                bias = B1b; outp = g_b1h;
            } else if (jid == 1) {
                warp_gemm8(h + (size_t)row0 * D, g_wT + 1 * D * D, c0, acc);
                bias = B2b; outp = g_b2h;
            } else if (jid == 2) {
                warp_gemm8(h + (size_t)row0 * D, g_wT + 2 * D * D, c0, acc);
                bias = A1b; outp = g_a1h;
            } else if (jid == 3) {
                warp_gemm8(p + (size_t)row0 * D, g_wT + 3 * D * D, c0, acc);
                bias = C1b; outp = g_c1p;
            } else if (jid == 4) {
                warp_gemm8(p + (size_t)row0 * D, g_wT + 4 * D * D, c0, acc);
                bias = C2b; outp = g_c2p;
            } else {
                warp_gemm8(h + (size_t)row0 * D, g_wT + 5 * D * D, c0, acc);
                warp_gemm8(p + (size_t)row0 * D, g_wT + 6 * D * D, c0, acc);
                bias = A2b; outp = g_v;
            }
            float4 bb = *(const float4*)(bias + c0);
#pragma unroll
            for (int j = 0; j < 8; j++) {
                float2 lo = upk2(acc[j][0]);
                float2 hi = upk2(acc[j][1]);
                float4 r = make_float4(lo.x + bb.x, lo.y + bb.y, hi.x + bb.z, hi.y + bb.w);
                *(float4*)(outp + (size_t)(row0 + j) * D + c0) = r;
            }
            job = __shfl_sync(FULL, next, 0);
        }
    }
    grid_barrier();

    // ---------------- Ph2: per-block scan + atomic global base ----------------
    {
        int base = bid * CHUNK;
        int cnt  = NN - base; if (cnt > CHUNK) cnt = CHUNK; if (cnt < 0) cnt = 0;
        for (int i = tid; i < 512; i += NTHR) s_scan[i] = (i < cnt) ? g_deg[base + i] : 0;
        __syncthreads();
        int* a  = s_scan;
        int* b2 = s_scan2;
        for (int d0 = 1; d0 < 512; d0 <<= 1) {
            for (int i = tid; i < 512; i += NTHR) {
                int v = a[i];
                if (i >= d0) v += a[i - d0];
                b2[i] = v;
            }
            __syncthreads();
            int* t = a; a = b2; b2 = t;
        }
        if (tid == 0) s_off = atomicAdd(&g_gbase, a[511]);
        __syncthreads();
        int off = s_off;
        for (int i = tid; i < cnt; i += NTHR) {
            int dgv = g_deg[base + i];
            int v = a[i] - dgv + off;
            g_start[base + i]  = v;
            g_cursor[base + i] = v;
            g_remain[base + i] = dgv;
        }
    }
    grid_barrier();

    // ---------------- Ph3: CSR record scatter ----------------
    for (int ei = gtid; ei < NE; ei += gstr) {
        int t_  = dst[ei];
        int pos = atomicAdd(&g_cursor[t_], 1);
        g_rec[pos] = make_int2(src[ei], ei);
    }
    grid_barrier();

    // ---------------- Ph4: edge GEMM + countdown-triggered aggregation --------
    {
        if (tid < D) { sA[tid] = 0.f; sB[tid] = 0.f; sC[tid] = 0.f; sD[tid] = 0.f; }
        __syncthreads();

        float4 hs = make_float4(0.f, 0.f, 0.f, 0.f);   // h stats (sum)
        float4 hq = make_float4(0.f, 0.f, 0.f, 0.f);   // h stats (sumsq)

        // deg-0 nodes (no incoming edges): process immediately
        for (int base = gw * 32; base < NN; base += NW * 32) {
            int n = base + lane;
            int dgv = (n < NN) ? g_deg[n] : 1;
            unsigned mask = __ballot_sync(FULL, dgv == 0);
            while (mask) {
                int b = __ffs(mask) - 1;
                mask &= mask - 1;
                agg_node(base + b, c0, lane, ehat, p, p_out, hs, hq);
            }
        }

        float es0 = 0.f, es1 = 0.f, es2 = 0.f, es3 = 0.f;   // e stats
        float eq0 = 0.f, eq1 = 0.f, eq2 = 0.f, eq3 = 0.f;
        const float* wT = g_wT + 7 * D * D;
        float4 bb = *(const float4*)(B3b + c0);
        const int NSTRIP = NE / 8;     // 75000
        int strip = 0;
        if (lane == 0) strip = atomicAdd(&g_ctr4, 1);
        strip = __shfl_sync(FULL, strip, 0);
        while (strip < NSTRIP) {
            int next = 0;
            if (lane == 0) next = atomicAdd(&g_ctr4, 1);

            int row0 = strip * 8;
            unsigned long long acc[8][2];
#pragma unroll
            for (int j = 0; j < 8; j++) { acc[j][0] = 0ull; acc[j][1] = 0ull; }
            warp_gemm8(e + (size_t)row0 * D, wT, c0, acc);
#pragma unroll
            for (int j = 0; j < 8; j++) {
                int er = row0 + j;
                int s_ = src[er];
                int t_ = dst[er];
                float4 g1 = *(const float4*)(g_b1h + (size_t)s_ * D + c0);
                float4 g2 = *(const float4*)(g_b2h + (size_t)t_ * D + c0);
                float2 lo = upk2(acc[j][0]);
                float2 hi = upk2(acc[j][1]);
                float4 r;
                r.x = lo.x + g1.x + g2.x + bb.x;
                r.y = lo.y + g1.y + g2.y + bb.y;
                r.z = hi.x + g1.z + g2.z + bb.z;
                r.w = hi.y + g1.w + g2.w + bb.w;
                *(float4*)(ehat + (size_t)er * D + c0) = r;     // sequential
                es0 += r.x; eq0 += r.x * r.x;
                es1 += r.y; eq1 += r.y * r.y;
                es2 += r.z; eq2 += r.z * r.z;
                es3 += r.w; eq3 += r.w * r.w;
            }
            __threadfence();   // make this strip's hat rows visible before countdown
#pragma unroll
            for (int j = 0; j < 8; j++) {
                int er = row0 + j;
                int t_ = dst[er];
                int old = 0;
                if (lane == 0) old = atomicSub(&g_remain[t_], 1);
                old = __shfl_sync(FULL, old, 0);
                if (old == 1) {
                    // this warp completed node t_'s last edge -> aggregate now
                    agg_node(t_, c0, lane, ehat, p, p_out, hs, hq);
                }
            }
            strip = __shfl_sync(FULL, next, 0);
        }

        atomicAdd(&sA[c0 + 0], es0); atomicAdd(&sB[c0 + 0], eq0);
        atomicAdd(&sA[c0 + 1], es1); atomicAdd(&sB[c0 + 1], eq1);
        atomicAdd(&sA[c0 + 2], es2); atomicAdd(&sB[c0 + 2], eq2);
        atomicAdd(&sA[c0 + 3], es3); atomicAdd(&sB[c0 + 3], eq3);
        atomicAdd(&sC[c0 + 0], hs.x); atomicAdd(&sD[c0 + 0], hq.x);
        atomicAdd(&sC[c0 + 1], hs.y); atomicAdd(&sD[c0 + 1], hq.y);
        atomicAdd(&sC[c0 + 2], hs.z); atomicAdd(&sD[c0 + 2], hq.z);
        atomicAdd(&sC[c0 + 3], hs.w); atomicAdd(&sD[c0 + 3], hq.w);
        __syncthreads();
        if (tid < D) {
            atomicAdd(&g_stats[tid],         sA[tid]);
            atomicAdd(&g_stats[D + tid],     sB[tid]);
            atomicAdd(&g_stats[2 * D + tid], sC[tid]);
            atomicAdd(&g_stats[3 * D + tid], sD[tid]);
        }
    }
    grid_barrier();

    // ---------------- Ph5: BN scale/shift + both output streams ----------------
    {
        if (tid < D) {
            float me  = g_stats[tid] * (1.0f / NE);
            float ve  = g_stats[D + tid] * (1.0f / NE) - me * me;
            float sce = bn_e_g[tid] * rsqrtf(ve + EPS_BN);
            s_ss[tid]         = sce;
            s_ss[D + tid]     = bn_e_b[tid] - me * sce;
            float mh  = g_stats[2 * D + tid] * (1.0f / NN);
            float vh  = g_stats[3 * D + tid] * (1.0f / NN) - mh * mh;
            float sch = bn_h_g[tid] * rsqrtf(vh + EPS_BN);
            s_ss[2 * D + tid] = sch;
            s_ss[3 * D + tid] = bn_h_b[tid] - mh * sch;
        }
        __syncthreads();

        // h_out = h + relu(bn(h_new))
        for (int i = gtid; i < NN * 32; i += gstr) {
            int c = (i & 31) * 4;
            float4 sc = *(float4*)(s_ss + 2 * D + c);
            float4 sh = *(float4*)(s_ss + 3 * D + c);
            float4 hn = ((const float4*)g_agg_h)[i];
            float4 hv = ((const float4*)h)[i];
            float4 o;
            o.x = hv.x + fmaxf(fmaf(hn.x, sc.x, sh.x), 0.f);
            o.y = hv.y + fmaxf(fmaf(hn.y, sc.y, sh.y), 0.f);
            o.z = hv.z + fmaxf(fmaf(hn.z, sc.z, sh.z), 0.f);
            o.w = hv.w + fmaxf(fmaf(hn.w, sc.w, sh.w), 0.f);
            ((float4*)h_out)[i] = o;
        }
        // e_out = e + relu(bn(hat)) — pure streaming, in place over ehat
        for (int i = gtid; i < NE * 32; i += gstr) {
            int c = (i & 31) * 4;
            float4 sc = *(float4*)(s_ss + c);
            float4 sh = *(float4*)(s_ss + D + c);
            float4 hn = ((const float4*)ehat)[i];
            float4 ev = ((const float4*)e)[i];
            float4 o;
            o.x = ev.x + fmaxf(fmaf(hn.x, sc.x, sh.x), 0.f);
            o.y = ev.y + fmaxf(fmaf(hn.y, sc.y, sh.y), 0.f);
            o.z = ev.z + fmaxf(fmaf(hn.z, sc.z, sh.z), 0.f);
            o.w = ev.w + fmaxf(fmaf(hn.w, sc.w, sh.w), 0.f);
            ((float4*)ehat)[i] = o;
        }
    }
}

// ---------------- launch -------------------------------------------------------
extern "C" void kernel_launch(void* const* d_in, const int* in_sizes, int n_in,
                              void* d_out, int out_size)
{
    const float* h   = (const float*)d_in[0];
    const float* e   = (const float*)d_in[1];
    const float* p   = (const float*)d_in[2];
    const int*   src = (const int*)d_in[3];
    const int*   dst = (const int*)d_in[4];
    const float* A1w = (const float*)d_in[5];
    const float* A1b = (const float*)d_in[6];
    const float* A2w = (const float*)d_in[7];
    const float* A2b = (const float*)d_in[8];
    const float* B1w = (const float*)d_in[9];
    const float* B1b = (const float*)d_in[10];
    const float* B2w = (const float*)d_in[11];
    const float* B2b = (const float*)d_in[12];
    const float* B3w = (const float*)d_in[13];
    const float* B3b = (const float*)d_in[14];
    const float* C1w = (const float*)d_in[15];
    const float* C1b = (const float*)d_in[16];
    const float* C2w = (const float*)d_in[17];
    const float* C2b = (const float*)d_in[18];
    const float* bn_h_g = (const float*)d_in[19];
    const float* bn_h_b = (const float*)d_in[20];
    const float* bn_e_g = (const float*)d_in[21];
    const float* bn_e_b = (const float*)d_in[22];

    float* out   = (float*)d_out;
    float* h_out = out;
    float* ehat  = out + (size_t)NN * D;
    float* p_out = out + (size_t)(NN + NE) * D;

    fused_gcn<<<NBLK, NTHR>>>(h, e, p, src, dst,
                              A1w, A1b, A2w, A2b,
                              B1w, B1b, B2w, B2b, B3w, B3b,
                              C1w, C1b, C2w, C2b,
                              bn_h_g, bn_h_b, bn_e_g, bn_e_b,
                              h_out, ehat, p_out);

    (void)in_sizes; (void)n_in; (void)out_size;
}

// round 15
// speedup vs baseline: 1.2291x; 1.2291x over previous
#include <cuda_runtime.h>
#include <math.h>

#define D       128
#define NN      50000
#define NE      600000
#define EPS_BN  1e-5f
#define EPS_ETA 1e-6f
#define NBLK    148
#define NTHR    1024
#define NWARP   32
#define CHUNK   338          // ceil(NN / NBLK)

// ---------------- device-global scratch (no allocations allowed) -------------
__device__ float g_wT[8 * D * D];     // transposed weights: [k*D + c]
__device__ float g_b1h[NN * D];
__device__ float g_b2h[NN * D];
__device__ float g_a1h[NN * D];
__device__ float g_v[NN * D];
__device__ float g_c1p[NN * D];
__device__ float g_c2p[NN * D];
__device__ float g_agg_h[NN * D];     // h_new
__device__ int2  g_rec[NE];           // (src, eid) in dst-sorted (CSR) order
__device__ float g_stats[4 * D];      // e_sum, e_sq, h_sum, h_sq
__device__ int   g_deg[NN];
__device__ int   g_start[NN];
__device__ int   g_cursor[NN];
__device__ int   g_gbase = 0;
__device__ int   g_ctr1 = 0;          // work-steal counters
__device__ int   g_ctr4 = 0;
__device__ int   g_ctr5 = 0;
__device__ int            g_bar_count = 0;
__device__ volatile int   g_bar_gen   = 0;

__device__ __forceinline__ float sigf(float x) {
    return __fdividef(1.0f, 1.0f + __expf(-x));
}
__device__ __forceinline__ float tanh_fast(float x) {
    x = fminf(15.0f, fmaxf(-15.0f, x));
    float t = __expf(2.0f * x);
    return __fdividef(t - 1.0f, t + 1.0f);
}

// ---------------- software grid barrier (all NBLK blocks co-resident) --------
__device__ __forceinline__ void grid_barrier()
{
    __syncthreads();
    if (threadIdx.x == 0) {
        int gen = g_bar_gen;
        __threadfence();
        if (atomicAdd(&g_bar_count, 1) == NBLK - 1) {
            g_bar_count = 0;
            __threadfence();
            g_bar_gen = gen + 1;
        } else {
            while (g_bar_gen == gen) { __nanosleep(64); }
        }
        __threadfence();
    }
    __syncthreads();
}

// ---------------- packed f32x2 helpers (sm_103a) -------------------------------
__device__ __forceinline__ unsigned long long pk2(float a, float b) {
    unsigned long long r;
    asm("mov.b64 %0, {%1, %2};" : "=l"(r) : "f"(a), "f"(b));
    return r;
}
__device__ __forceinline__ float2 upk2(unsigned long long v) {
    float2 r;
    asm("mov.b64 {%0, %1}, %2;" : "=f"(r.x), "=f"(r.y) : "l"(v));
    return r;
}
__device__ __forceinline__ unsigned long long ffma2(
    unsigned long long a, unsigned long long b, unsigned long long c) {
    unsigned long long d;
    asm("fma.rn.f32x2 %0, %1, %2, %3;" : "=l"(d) : "l"(a), "l"(b), "l"(c));
    return d;
}

// ---------------- sync-free warp GEMM: 8 rows x 128 cols, K=128 ----------------
__device__ __forceinline__ void warp_gemm8(
    const float* __restrict__ Xr,
    const float* __restrict__ wT,
    int c0, unsigned long long acc[8][2])
{
    for (int k = 0; k < D; k += 4) {
        ulonglong2 w0 = *(const ulonglong2*)(wT + (size_t)(k + 0) * D + c0);
        ulonglong2 w1 = *(const ulonglong2*)(wT + (size_t)(k + 1) * D + c0);
        ulonglong2 w2 = *(const ulonglong2*)(wT + (size_t)(k + 2) * D + c0);
        ulonglong2 w3 = *(const ulonglong2*)(wT + (size_t)(k + 3) * D + c0);
#pragma unroll
        for (int j = 0; j < 8; j++) {
            float4 xv = *(const float4*)(Xr + (size_t)j * D + k);
            unsigned long long b;
            b = pk2(xv.x, xv.x);
            acc[j][0] = ffma2(b, w0.x, acc[j][0]);
            acc[j][1] = ffma2(b, w0.y, acc[j][1]);
            b = pk2(xv.y, xv.y);
            acc[j][0] = ffma2(b, w1.x, acc[j][0]);
            acc[j][1] = ffma2(b, w1.y, acc[j][1]);
            b = pk2(xv.z, xv.z);
            acc[j][0] = ffma2(b, w2.x, acc[j][0]);
            acc[j][1] = ffma2(b, w2.y, acc[j][1]);
            b = pk2(xv.w, xv.w);
            acc[j][0] = ffma2(b, w3.x, acc[j][0]);
            acc[j][1] = ffma2(b, w3.y, acc[j][1]);
        }
    }
}

// =============================================================================
// Single fused persistent kernel. grid = 148 x 1024.
// =============================================================================
__global__ void __launch_bounds__(NTHR) fused_gcn(
    const float* __restrict__ h, const float* __restrict__ e, const float* __restrict__ p,
    const int* __restrict__ src, const int* __restrict__ dst,
    const float* __restrict__ A1w, const float* __restrict__ A1b,
    const float* __restrict__ A2w, const float* __restrict__ A2b,
    const float* __restrict__ B1w, const float* __restrict__ B1b,
    const float* __restrict__ B2w, const float* __restrict__ B2b,
    const float* __restrict__ B3w, const float* __restrict__ B3b,
    const float* __restrict__ C1w, const float* __restrict__ C1b,
    const float* __restrict__ C2w, const float* __restrict__ C2b,
    const float* __restrict__ bn_h_g, const float* __restrict__ bn_h_b,
    const float* __restrict__ bn_e_g, const float* __restrict__ bn_e_b,
    float* __restrict__ h_out, float* __restrict__ ehat, float* __restrict__ p_out)
{
    __shared__ int   s_scan[512];
    __shared__ int   s_scan2[512];
    __shared__ float sA[D];
    __shared__ float sB[D];
    __shared__ float s_ss[2 * D];
    __shared__ int   s_off;

    const int tid  = threadIdx.x;
    const int lane = tid & 31;
    const int warp = tid >> 5;
    const int bid  = blockIdx.x;
    const int c0   = lane * 4;
    const int gtid = bid * NTHR + tid;
    const int gstr = NBLK * NTHR;          // 151552
    const unsigned FULL = 0xFFFFFFFFu;

    // ---------------- Ph0: zero deg/stats/counters + weight transpose ---------
    for (int i = gtid; i < NN; i += gstr) g_deg[i] = 0;
    if (gtid < 4 * D) g_stats[gtid] = 0.f;
    if (gtid == 0) { g_gbase = 0; g_ctr1 = 0; g_ctr4 = 0; g_ctr5 = 0; }
    for (int i = gtid; i < 8 * D * D; i += gstr) {
        int j   = i >> 14;
        int rem = i & 16383;
        int k   = rem >> 7;
        int c   = rem & 127;
        float v;
        if      (j == 0) v = B1w[c * D + k];
        else if (j == 1) v = B2w[c * D + k];
        else if (j == 2) v = A1w[c * D + k];
        else if (j == 3) v = C1w[c * D + k];
        else if (j == 4) v = C2w[c * D + k];
        else if (j == 5) v = A2w[c * 2 * D + k];
        else if (j == 6) v = A2w[c * 2 * D + D + k];
        else             v = B3w[c * D + k];
        g_wT[i] = v;
    }
    grid_barrier();

    // ---------------- Ph1: dst histogram + node GEMMs (work-stealing x2) ------
    for (int ei = gtid; ei < NE; ei += gstr) atomicAdd(&g_deg[dst[ei]], 1);
    {
        const int NSTRIP = NN / 8;     // 6250
        const int NJOB   = 6 * NSTRIP;
        int jb = 0;
        if (lane == 0) jb = atomicAdd(&g_ctr1, 2);
        jb = __shfl_sync(FULL, jb, 0);
        while (jb < NJOB) {
            int nxt = 0;
            if (lane == 0) nxt = atomicAdd(&g_ctr1, 2);

            int jend = jb + 2; if (jend > NJOB) jend = NJOB;
            for (int job = jb; job < jend; job++) {
                int jid   = job / NSTRIP;
                int strip = job - jid * NSTRIP;
                int row0  = strip * 8;
                unsigned long long acc[8][2];
#pragma unroll
                for (int j = 0; j < 8; j++) { acc[j][0] = 0ull; acc[j][1] = 0ull; }

                const float* bias;
                float* outp;
                if (jid == 0) {
                    warp_gemm8(h + (size_t)row0 * D, g_wT + 0 * D * D, c0, acc);
                    bias = B1b; outp = g_b1h;
                } else if (jid == 1) {
                    warp_gemm8(h + (size_t)row0 * D, g_wT + 1 * D * D, c0, acc);
                    bias = B2b; outp = g_b2h;
                } else if (jid == 2) {
                    warp_gemm8(h + (size_t)row0 * D, g_wT + 2 * D * D, c0, acc);
                    bias = A1b; outp = g_a1h;
                } else if (jid == 3) {
                    warp_gemm8(p + (size_t)row0 * D, g_wT + 3 * D * D, c0, acc);
                    bias = C1b; outp = g_c1p;
                } else if (jid == 4) {
                    warp_gemm8(p + (size_t)row0 * D, g_wT + 4 * D * D, c0, acc);
                    bias = C2b; outp = g_c2p;
                } else {
                    warp_gemm8(h + (size_t)row0 * D, g_wT + 5 * D * D, c0, acc);
                    warp_gemm8(p + (size_t)row0 * D, g_wT + 6 * D * D, c0, acc);
                    bias = A2b; outp = g_v;
                }
                float4 bb = *(const float4*)(bias + c0);
#pragma unroll
                for (int j = 0; j < 8; j++) {
                    float2 lo = upk2(acc[j][0]);
                    float2 hi = upk2(acc[j][1]);
                    float4 r = make_float4(lo.x + bb.x, lo.y + bb.y, hi.x + bb.z, hi.y + bb.w);
                    *(float4*)(outp + (size_t)(row0 + j) * D + c0) = r;
                }
            }
            jb = __shfl_sync(FULL, nxt, 0);
        }
    }
    grid_barrier();

    // ---------------- Ph2: per-block scan + atomic global base ----------------
    {
        int base = bid * CHUNK;
        int cnt  = NN - base; if (cnt > CHUNK) cnt = CHUNK; if (cnt < 0) cnt = 0;
        for (int i = tid; i < 512; i += NTHR) s_scan[i] = (i < cnt) ? g_deg[base + i] : 0;
        __syncthreads();
        int* a  = s_scan;
        int* b2 = s_scan2;
        for (int d0 = 1; d0 < 512; d0 <<= 1) {
            for (int i = tid; i < 512; i += NTHR) {
                int v = a[i];
                if (i >= d0) v += a[i - d0];
                b2[i] = v;
            }
            __syncthreads();
            int* t = a; a = b2; b2 = t;
        }
        if (tid == 0) s_off = atomicAdd(&g_gbase, a[511]);
        __syncthreads();
        int off = s_off;
        for (int i = tid; i < cnt; i += NTHR) {
            int v = a[i] - g_deg[base + i] + off;   // exclusive + global base
            g_start[base + i]  = v;
            g_cursor[base + i] = v;
        }
    }
    grid_barrier();

    // ---------------- Ph4: edge GEMM (steal x2) + CSR record scatter + e-stats
    {
        if (tid < D) { sA[tid] = 0.f; sB[tid] = 0.f; }
        __syncthreads();

        float ps0 = 0.f, ps1 = 0.f, ps2 = 0.f, ps3 = 0.f;
        float pq0 = 0.f, pq1 = 0.f, pq2 = 0.f, pq3 = 0.f;
        const float* wT = g_wT + 7 * D * D;
        float4 bb = *(const float4*)(B3b + c0);
        const int NSTRIP = NE / 8;     // 75000
        int sb = 0;
        if (lane == 0) sb = atomicAdd(&g_ctr4, 2);
        sb = __shfl_sync(FULL, sb, 0);
        while (sb < NSTRIP) {
            int nxt = 0;
            if (lane == 0) nxt = atomicAdd(&g_ctr4, 2);

            int send = sb + 2; if (send > NSTRIP) send = NSTRIP;
            for (int strip = sb; strip < send; strip++) {
                int row0 = strip * 8;
                unsigned long long acc[8][2];
#pragma unroll
                for (int j = 0; j < 8; j++) { acc[j][0] = 0ull; acc[j][1] = 0ull; }
                warp_gemm8(e + (size_t)row0 * D, wT, c0, acc);
#pragma unroll
                for (int j = 0; j < 8; j++) {
                    int er = row0 + j;
                    int s_ = src[er];
                    int t_ = dst[er];
                    float4 g1 = *(const float4*)(g_b1h + (size_t)s_ * D + c0);
                    float4 g2 = *(const float4*)(g_b2h + (size_t)t_ * D + c0);
                    float2 lo = upk2(acc[j][0]);
                    float2 hi = upk2(acc[j][1]);
                    float4 r;
                    r.x = lo.x + g1.x + g2.x + bb.x;
                    r.y = lo.y + g1.y + g2.y + bb.y;
                    r.z = hi.x + g1.z + g2.z + bb.z;
                    r.w = hi.y + g1.w + g2.w + bb.w;
                    *(float4*)(ehat + (size_t)er * D + c0) = r;     // sequential
                    if (lane == 0) {
                        int pos = atomicAdd(&g_cursor[t_], 1);
                        g_rec[pos] = make_int2(s_, er);             // 8B scatter
                    }
                    ps0 += r.x; pq0 += r.x * r.x;
                    ps1 += r.y; pq1 += r.y * r.y;
                    ps2 += r.z; pq2 += r.z * r.z;
                    ps3 += r.w; pq3 += r.w * r.w;
                }
            }
            sb = __shfl_sync(FULL, nxt, 0);
        }
        atomicAdd(&sA[c0 + 0], ps0); atomicAdd(&sB[c0 + 0], pq0);
        atomicAdd(&sA[c0 + 1], ps1); atomicAdd(&sB[c0 + 1], pq1);
        atomicAdd(&sA[c0 + 2], ps2); atomicAdd(&sB[c0 + 2], pq2);
        atomicAdd(&sA[c0 + 3], ps3); atomicAdd(&sB[c0 + 3], pq3);
        __syncthreads();
        if (tid < D) {
            atomicAdd(&g_stats[tid], sA[tid]);
            atomicAdd(&g_stats[D + tid], sB[tid]);
        }
    }
    grid_barrier();

    // ---------------- Ph5: aggregation + fused e_final (steal, shfl recs) -----
    {
        if (tid < D) {
            float me  = g_stats[tid] * (1.0f / NE);
            float ve  = g_stats[D + tid] * (1.0f / NE) - me * me;
            float sce = bn_e_g[tid] * rsqrtf(ve + EPS_BN);
            s_ss[tid]     = sce;
            s_ss[D + tid] = bn_e_b[tid] - me * sce;
            sA[tid] = 0.f; sB[tid] = 0.f;
        }
        __syncthreads();
        const float4 sce = *(const float4*)(s_ss + c0);
        const float4 she = *(const float4*)(s_ss + D + c0);

        float ps0 = 0.f, ps1 = 0.f, ps2 = 0.f, ps3 = 0.f;
        float pq0 = 0.f, pq1 = 0.f, pq2 = 0.f, pq3 = 0.f;

        for (;;) {
            int nbase = 0;
            if (lane == 0) nbase = atomicAdd(&g_ctr5, 4);
            nbase = __shfl_sync(FULL, nbase, 0);
            if (nbase >= NN) break;
            int nend = nbase + 4; if (nend > NN) nend = NN;

            for (int n = nbase; n < nend; n++) {
                int st = g_start[n];
                int dg = g_deg[n];
                float4 ss = make_float4(0.f, 0.f, 0.f, 0.f);
                float4 ah = make_float4(0.f, 0.f, 0.f, 0.f);
                float4 ap = make_float4(0.f, 0.f, 0.f, 0.f);

                int done = 0;
                while (done < dg) {
                    int m = dg - done; if (m > 32) m = 32;
                    int2 rr = make_int2(0, 0);
                    if (lane < m) rr = g_rec[st + done + lane];
                    int j = 0;
                    for (; j + 2 <= m; j += 2) {
                        int sa = __shfl_sync(FULL, rr.x, j);
                        int ea = __shfl_sync(FULL, rr.y, j);
                        int sb_ = __shfl_sync(FULL, rr.x, j + 1);
                        int eb = __shfl_sync(FULL, rr.y, j + 1);
                        const float4 hva = *(const float4*)(ehat + (size_t)ea * D + c0);
                        const float4 hvb = *(const float4*)(ehat + (size_t)eb * D + c0);
                        const float4 vva = *(const float4*)(g_v + (size_t)sa * D + c0);
                        const float4 vvb = *(const float4*)(g_v + (size_t)sb_ * D + c0);
                        const float4 cpa = *(const float4*)(g_c2p + (size_t)sa * D + c0);
                        const float4 cpb = *(const float4*)(g_c2p + (size_t)sb_ * D + c0);
                        const float4 eva = *(const float4*)(e + (size_t)ea * D + c0);
                        const float4 evb = *(const float4*)(e + (size_t)eb * D + c0);
                        float a0 = sigf(hva.x), a1 = sigf(hva.y), a2 = sigf(hva.z), a3 = sigf(hva.w);
                        float b0 = sigf(hvb.x), b1 = sigf(hvb.y), b2 = sigf(hvb.z), b3 = sigf(hvb.w);
                        ss.x += a0 + b0; ss.y += a1 + b1; ss.z += a2 + b2; ss.w += a3 + b3;
                        ah.x = fmaf(a0, vva.x, fmaf(b0, vvb.x, ah.x));
                        ah.y = fmaf(a1, vva.y, fmaf(b1, vvb.y, ah.y));
                        ah.z = fmaf(a2, vva.z, fmaf(b2, vvb.z, ah.z));
                        ah.w = fmaf(a3, vva.w, fmaf(b3, vvb.w, ah.w));
                        ap.x = fmaf(a0, cpa.x, fmaf(b0, cpb.x, ap.x));
                        ap.y = fmaf(a1, cpa.y, fmaf(b1, cpb.y, ap.y));
                        ap.z = fmaf(a2, cpa.z, fmaf(b2, cpb.z, ap.z));
                        ap.w = fmaf(a3, cpa.w, fmaf(b3, cpb.w, ap.w));
                        float4 eo;
                        eo.x = eva.x + fmaxf(fmaf(hva.x, sce.x, she.x), 0.f);
                        eo.y = eva.y + fmaxf(fmaf(hva.y, sce.y, she.y), 0.f);
                        eo.z = eva.z + fmaxf(fmaf(hva.z, sce.z, she.z), 0.f);
                        eo.w = eva.w + fmaxf(fmaf(hva.w, sce.w, she.w), 0.f);
                        *(float4*)(ehat + (size_t)ea * D + c0) = eo;
                        eo.x = evb.x + fmaxf(fmaf(hvb.x, sce.x, she.x), 0.f);
                        eo.y = evb.y + fmaxf(fmaf(hvb.y, sce.y, she.y), 0.f);
                        eo.z = evb.z + fmaxf(fmaf(hvb.z, sce.z, she.z), 0.f);
                        eo.w = evb.w + fmaxf(fmaf(hvb.w, sce.w, she.w), 0.f);
                        *(float4*)(ehat + (size_t)eb * D + c0) = eo;
                    }
                    if (j < m) {
                        int sa = __shfl_sync(FULL, rr.x, j);
                        int ea = __shfl_sync(FULL, rr.y, j);
                        const float4 hv = *(const float4*)(ehat + (size_t)ea * D + c0);
                        const float4 vv = *(const float4*)(g_v + (size_t)sa * D + c0);
                        const float4 cp = *(const float4*)(g_c2p + (size_t)sa * D + c0);
                        const float4 ev = *(const float4*)(e + (size_t)ea * D + c0);
                        float s0 = sigf(hv.x), s1 = sigf(hv.y), s2 = sigf(hv.z), s3 = sigf(hv.w);
                        ss.x += s0; ss.y += s1; ss.z += s2; ss.w += s3;
                        ah.x = fmaf(s0, vv.x, ah.x);
                        ah.y = fmaf(s1, vv.y, ah.y);
                        ah.z = fmaf(s2, vv.z, ah.z);
                        ah.w = fmaf(s3, vv.w, ah.w);
                        ap.x = fmaf(s0, cp.x, ap.x);
                        ap.y = fmaf(s1, cp.y, ap.y);
                        ap.z = fmaf(s2, cp.z, ap.z);
                        ap.w = fmaf(s3, cp.w, ap.w);
                        float4 eo;
                        eo.x = ev.x + fmaxf(fmaf(hv.x, sce.x, she.x), 0.f);
                        eo.y = ev.y + fmaxf(fmaf(hv.y, sce.y, she.y), 0.f);
                        eo.z = ev.z + fmaxf(fmaf(hv.z, sce.z, she.z), 0.f);
                        eo.w = ev.w + fmaxf(fmaf(hv.w, sce.w, she.w), 0.f);
                        *(float4*)(ehat + (size_t)ea * D + c0) = eo;
                    }
                    done += m;
                }
                float i0 = __fdividef(1.0f, ss.x + EPS_ETA);
                float i1 = __fdividef(1.0f, ss.y + EPS_ETA);
                float i2 = __fdividef(1.0f, ss.z + EPS_ETA);
                float i3 = __fdividef(1.0f, ss.w + EPS_ETA);

                size_t off = (size_t)n * D + c0;
                float4 a1v = *(const float4*)(g_a1h + off);
                float4 hn = make_float4(fmaf(ah.x, i0, a1v.x), fmaf(ah.y, i1, a1v.y),
                                        fmaf(ah.z, i2, a1v.z), fmaf(ah.w, i3, a1v.w));
                *(float4*)(g_agg_h + off) = hn;
                ps0 += hn.x; pq0 += hn.x * hn.x;
                ps1 += hn.y; pq1 += hn.y * hn.y;
                ps2 += hn.z; pq2 += hn.z * hn.z;
                ps3 += hn.w; pq3 += hn.w * hn.w;

                float4 c1 = *(const float4*)(g_c1p + off);
                float4 pv = *(const float4*)(p + off);
                float4 po;
                po.x = pv.x + tanh_fast(fmaf(ap.x, i0, c1.x));
                po.y = pv.y + tanh_fast(fmaf(ap.y, i1, c1.y));
                po.z = pv.z + tanh_fast(fmaf(ap.z, i2, c1.z));
                po.w = pv.w + tanh_fast(fmaf(ap.w, i3, c1.w));
                *(float4*)(p_out + off) = po;
            }
        }
        atomicAdd(&sA[c0 + 0], ps0); atomicAdd(&sB[c0 + 0], pq0);
        atomicAdd(&sA[c0 + 1], ps1); atomicAdd(&sB[c0 + 1], pq1);
        atomicAdd(&sA[c0 + 2], ps2); atomicAdd(&sB[c0 + 2], pq2);
        atomicAdd(&sA[c0 + 3], ps3); atomicAdd(&sB[c0 + 3], pq3);
        __syncthreads();
        if (tid < D) {
            atomicAdd(&g_stats[2 * D + tid], sA[tid]);
            atomicAdd(&g_stats[3 * D + tid], sB[tid]);
        }
    }
    grid_barrier();

    // ---------------- Ph6: h BN + h_out stream ----------------
    {
        if (tid < D) {
            float mh  = g_stats[2 * D + tid] * (1.0f / NN);
            float vh  = g_stats[3 * D + tid] * (1.0f / NN) - mh * mh;
            float sch = bn_h_g[tid] * rsqrtf(vh + EPS_BN);
            s_ss[tid]     = sch;
            s_ss[D + tid] = bn_h_b[tid] - mh * sch;
        }
        __syncthreads();

        for (int i = gtid; i < NN * 32; i += gstr) {
            int c = (i & 31) * 4;
            float4 sc = *(float4*)(s_ss + c);
            float4 sh = *(float4*)(s_ss + D + c);
            float4 hn = ((const float4*)g_agg_h)[i];
            float4 hv = ((const float4*)h)[i];
            float4 o;
            o.x = hv.x + fmaxf(fmaf(hn.x, sc.x, sh.x), 0.f);
            o.y = hv.y + fmaxf(fmaf(hn.y, sc.y, sh.y), 0.f);
            o.z = hv.z + fmaxf(fmaf(hn.z, sc.z, sh.z), 0.f);
            o.w = hv.w + fmaxf(fmaf(hn.w, sc.w, sh.w), 0.f);
            ((float4*)h_out)[i] = o;
        }
    }
}

// ---------------- launch -------------------------------------------------------
extern "C" void kernel_launch(void* const* d_in, const int* in_sizes, int n_in,
                              void* d_out, int out_size)
{
    const float* h   = (const float*)d_in[0];
    const float* e   = (const float*)d_in[1];
    const float* p   = (const float*)d_in[2];
    const int*   src = (const int*)d_in[3];
    const int*   dst = (const int*)d_in[4];
    const float* A1w = (const float*)d_in[5];
    const float* A1b = (const float*)d_in[6];
    const float* A2w = (const float*)d_in[7];
    const float* A2b = (const float*)d_in[8];
    const float* B1w = (const float*)d_in[9];
    const float* B1b = (const float*)d_in[10];
    const float* B2w = (const float*)d_in[11];
    const float* B2b = (const float*)d_in[12];
    const float* B3w = (const float*)d_in[13];
    const float* B3b = (const float*)d_in[14];
    const float* C1w = (const float*)d_in[15];
    const float* C1b = (const float*)d_in[16];
    const float* C2w = (const float*)d_in[17];
    const float* C2b = (const float*)d_in[18];
    const float* bn_h_g = (const float*)d_in[19];
    const float* bn_h_b = (const float*)d_in[20];
    const float* bn_e_g = (const float*)d_in[21];
    const float* bn_e_b = (const float*)d_in[22];

    float* out   = (float*)d_out;
    float* h_out = out;
    float* ehat  = out + (size_t)NN * D;
    float* p_out = out + (size_t)(NN + NE) * D;

    fused_gcn<<<NBLK, NTHR>>>(h, e, p, src, dst,
                              A1w, A1b, A2w, A2b,
                              B1w, B1b, B2w, B2b, B3w, B3b,
                              C1w, C1b, C2w, C2b,
                              bn_h_g, bn_h_b, bn_e_g, bn_e_b,
                              h_out, ehat, p_out);

    (void)in_sizes; (void)n_in; (void)out_size;
}

// round 16
// speedup vs baseline: 1.2705x; 1.0337x over previous
#include <cuda_runtime.h>
#include <cuda_fp16.h>
#include <math.h>

#define D       128
#define NN      50000
#define NE      600000
#define EPS_BN  1e-5f
#define EPS_ETA 1e-6f
#define NBLK    148
#define NTHR    1024
#define NWARP   32
#define CHUNK   338          // ceil(NN / NBLK)

// ---------------- device-global scratch (no allocations allowed) -------------
__device__ float  g_wT[8 * D * D];    // transposed weights: [k*D + c]
__device__ float  g_b1h[NN * D];
__device__ float  g_b2h[NN * D];
__device__ float  g_a1h[NN * D];
__device__ __half g_v16[NN * D];      // A2([h;p]) in fp16
__device__ float  g_c1p[NN * D];
__device__ __half g_c2p16[NN * D];    // C2 p in fp16
__device__ __half g_hat16[NE * D];    // raw hat_eta in fp16
__device__ float  g_agg_h[NN * D];    // h_new
__device__ int2   g_rec[NE];          // (src, eid) in dst-sorted (CSR) order
__device__ float  g_stats[4 * D];     // e_sum, e_sq, h_sum, h_sq
__device__ int    g_deg[NN];
__device__ int    g_start[NN];
__device__ int    g_cursor[NN];
__device__ int    g_gbase = 0;
__device__ int    g_ctr1 = 0;         // work-steal counters
__device__ int    g_ctr4 = 0;
__device__ int    g_ctr5 = 0;
__device__ int            g_bar_count = 0;
__device__ volatile int   g_bar_gen   = 0;

__device__ __forceinline__ float sigf(float x) {
    return __fdividef(1.0f, 1.0f + __expf(-x));
}
__device__ __forceinline__ float tanh_fast(float x) {
    x = fminf(15.0f, fmaxf(-15.0f, x));
    float t = __expf(2.0f * x);
    return __fdividef(t - 1.0f, t + 1.0f);
}

// fp16x4 pack/unpack via uint2
__device__ __forceinline__ uint2 pack_h4(float4 r) {
    __half2 a = __floats2half2_rn(r.x, r.y);
    __half2 b = __floats2half2_rn(r.z, r.w);
    uint2 u;
    u.x = *reinterpret_cast<unsigned*>(&a);
    u.y = *reinterpret_cast<unsigned*>(&b);
    return u;
}
__device__ __forceinline__ float4 unpack_h4(uint2 u) {
    __half2 a = *reinterpret_cast<__half2*>(&u.x);
    __half2 b = *reinterpret_cast<__half2*>(&u.y);
    float2 fa = __half22float2(a);
    float2 fb = __half22float2(b);
    return make_float4(fa.x, fa.y, fb.x, fb.y);
}

// ---------------- software grid barrier (all NBLK blocks co-resident) --------
__device__ __forceinline__ void grid_barrier()
{
    __syncthreads();
    if (threadIdx.x == 0) {
        int gen = g_bar_gen;
        __threadfence();
        if (atomicAdd(&g_bar_count, 1) == NBLK - 1) {
            g_bar_count = 0;
            __threadfence();
            g_bar_gen = gen + 1;
        } else {
            while (g_bar_gen == gen) { __nanosleep(64); }
        }
        __threadfence();
    }
    __syncthreads();
}

// ---------------- packed f32x2 helpers (sm_103a) -------------------------------
__device__ __forceinline__ unsigned long long pk2(float a, float b) {
    unsigned long long r;
    asm("mov.b64 %0, {%1, %2};" : "=l"(r) : "f"(a), "f"(b));
    return r;
}
__device__ __forceinline__ float2 upk2(unsigned long long v) {
    float2 r;
    asm("mov.b64 {%0, %1}, %2;" : "=f"(r.x), "=f"(r.y) : "l"(v));
    return r;
}
__device__ __forceinline__ unsigned long long ffma2(
    unsigned long long a, unsigned long long b, unsigned long long c) {
    unsigned long long d;
    asm("fma.rn.f32x2 %0, %1, %2, %3;" : "=l"(d) : "l"(a), "l"(b), "l"(c));
    return d;
}

// ---------------- sync-free warp GEMM: 8 rows x 128 cols, K=128 ----------------
__device__ __forceinline__ void warp_gemm8(
    const float* __restrict__ Xr,
    const float* __restrict__ wT,
    int c0, unsigned long long acc[8][2])
{
    for (int k = 0; k < D; k += 4) {
        ulonglong2 w0 = *(const ulonglong2*)(wT + (size_t)(k + 0) * D + c0);
        ulonglong2 w1 = *(const ulonglong2*)(wT + (size_t)(k + 1) * D + c0);
        ulonglong2 w2 = *(const ulonglong2*)(wT + (size_t)(k + 2) * D + c0);
        ulonglong2 w3 = *(const ulonglong2*)(wT + (size_t)(k + 3) * D + c0);
#pragma unroll
        for (int j = 0; j < 8; j++) {
            float4 xv = *(const float4*)(Xr + (size_t)j * D + k);
            unsigned long long b;
            b = pk2(xv.x, xv.x);
            acc[j][0] = ffma2(b, w0.x, acc[j][0]);
            acc[j][1] = ffma2(b, w0.y, acc[j][1]);
            b = pk2(xv.y, xv.y);
            acc[j][0] = ffma2(b, w1.x, acc[j][0]);
            acc[j][1] = ffma2(b, w1.y, acc[j][1]);
            b = pk2(xv.z, xv.z);
            acc[j][0] = ffma2(b, w2.x, acc[j][0]);
            acc[j][1] = ffma2(b, w2.y, acc[j][1]);
            b = pk2(xv.w, xv.w);
            acc[j][0] = ffma2(b, w3.x, acc[j][0]);
            acc[j][1] = ffma2(b, w3.y, acc[j][1]);
        }
    }
}

// =============================================================================
// Single fused persistent kernel. grid = 148 x 1024.
// =============================================================================
__global__ void __launch_bounds__(NTHR) fused_gcn(
    const float* __restrict__ h, const float* __restrict__ e, const float* __restrict__ p,
    const int* __restrict__ src, const int* __restrict__ dst,
    const float* __restrict__ A1w, const float* __restrict__ A1b,
    const float* __restrict__ A2w, const float* __restrict__ A2b,
    const float* __restrict__ B1w, const float* __restrict__ B1b,
    const float* __restrict__ B2w, const float* __restrict__ B2b,
    const float* __restrict__ B3w, const float* __restrict__ B3b,
    const float* __restrict__ C1w, const float* __restrict__ C1b,
    const float* __restrict__ C2w, const float* __restrict__ C2b,
    const float* __restrict__ bn_h_g, const float* __restrict__ bn_h_b,
    const float* __restrict__ bn_e_g, const float* __restrict__ bn_e_b,
    float* __restrict__ h_out, float* __restrict__ ehat, float* __restrict__ p_out)
{
    __shared__ int   s_scan[512];
    __shared__ int   s_scan2[512];
    __shared__ float sA[D];
    __shared__ float sB[D];
    __shared__ float s_ss[2 * D];
    __shared__ int   s_off;

    const int tid  = threadIdx.x;
    const int lane = tid & 31;
    const int warp = tid >> 5;
    const int bid  = blockIdx.x;
    const int c0   = lane * 4;
    const int gtid = bid * NTHR + tid;
    const int gstr = NBLK * NTHR;          // 151552
    const unsigned FULL = 0xFFFFFFFFu;

    // ---------------- Ph0: zero deg/stats/counters + weight transpose ---------
    for (int i = gtid; i < NN; i += gstr) g_deg[i] = 0;
    if (gtid < 4 * D) g_stats[gtid] = 0.f;
    if (gtid == 0) { g_gbase = 0; g_ctr1 = 0; g_ctr4 = 0; g_ctr5 = 0; }
    for (int i = gtid; i < 8 * D * D; i += gstr) {
        int j   = i >> 14;
        int rem = i & 16383;
        int k   = rem >> 7;
        int c   = rem & 127;
        float v;
        if      (j == 0) v = B1w[c * D + k];
        else if (j == 1) v = B2w[c * D + k];
        else if (j == 2) v = A1w[c * D + k];
        else if (j == 3) v = C1w[c * D + k];
        else if (j == 4) v = C2w[c * D + k];
        else if (j == 5) v = A2w[c * 2 * D + k];
        else if (j == 6) v = A2w[c * 2 * D + D + k];
        else             v = B3w[c * D + k];
        g_wT[i] = v;
    }
    grid_barrier();

    // ---------------- Ph1: dst histogram + node GEMMs (work-stealing x2) ------
    for (int ei = gtid; ei < NE; ei += gstr) atomicAdd(&g_deg[dst[ei]], 1);
    {
        const int NSTRIP = NN / 8;     // 6250
        const int NJOB   = 6 * NSTRIP;
        int jb = 0;
        if (lane == 0) jb = atomicAdd(&g_ctr1, 2);
        jb = __shfl_sync(FULL, jb, 0);
        while (jb < NJOB) {
            int nxt = 0;
            if (lane == 0) nxt = atomicAdd(&g_ctr1, 2);

            int jend = jb + 2; if (jend > NJOB) jend = NJOB;
            for (int job = jb; job < jend; job++) {
                int jid   = job / NSTRIP;
                int strip = job - jid * NSTRIP;
                int row0  = strip * 8;
                unsigned long long acc[8][2];
#pragma unroll
                for (int j = 0; j < 8; j++) { acc[j][0] = 0ull; acc[j][1] = 0ull; }

                const float* bias;
                float* outp = nullptr;
                __half* outp16 = nullptr;
                if (jid == 0) {
                    warp_gemm8(h + (size_t)row0 * D, g_wT + 0 * D * D, c0, acc);
                    bias = B1b; outp = g_b1h;
                } else if (jid == 1) {
                    warp_gemm8(h + (size_t)row0 * D, g_wT + 1 * D * D, c0, acc);
                    bias = B2b; outp = g_b2h;
                } else if (jid == 2) {
                    warp_gemm8(h + (size_t)row0 * D, g_wT + 2 * D * D, c0, acc);
                    bias = A1b; outp = g_a1h;
                } else if (jid == 3) {
                    warp_gemm8(p + (size_t)row0 * D, g_wT + 3 * D * D, c0, acc);
                    bias = C1b; outp = g_c1p;
                } else if (jid == 4) {
                    warp_gemm8(p + (size_t)row0 * D, g_wT + 4 * D * D, c0, acc);
                    bias = C2b; outp16 = g_c2p16;
                } else {
                    warp_gemm8(h + (size_t)row0 * D, g_wT + 5 * D * D, c0, acc);
                    warp_gemm8(p + (size_t)row0 * D, g_wT + 6 * D * D, c0, acc);
                    bias = A2b; outp16 = g_v16;
                }
                float4 bb = *(const float4*)(bias + c0);
#pragma unroll
                for (int j = 0; j < 8; j++) {
                    float2 lo = upk2(acc[j][0]);
                    float2 hi = upk2(acc[j][1]);
                    float4 r = make_float4(lo.x + bb.x, lo.y + bb.y, hi.x + bb.z, hi.y + bb.w);
                    if (outp16) {
                        *(uint2*)(outp16 + (size_t)(row0 + j) * D + c0) = pack_h4(r);
                    } else {
                        *(float4*)(outp + (size_t)(row0 + j) * D + c0) = r;
                    }
                }
            }
            jb = __shfl_sync(FULL, nxt, 0);
        }
    }
    grid_barrier();

    // ---------------- Ph2: per-block scan + atomic global base ----------------
    {
        int base = bid * CHUNK;
        int cnt  = NN - base; if (cnt > CHUNK) cnt = CHUNK; if (cnt < 0) cnt = 0;
        for (int i = tid; i < 512; i += NTHR) s_scan[i] = (i < cnt) ? g_deg[base + i] : 0;
        __syncthreads();
        int* a  = s_scan;
        int* b2 = s_scan2;
        for (int d0 = 1; d0 < 512; d0 <<= 1) {
            for (int i = tid; i < 512; i += NTHR) {
                int v = a[i];
                if (i >= d0) v += a[i - d0];
                b2[i] = v;
            }
            __syncthreads();
            int* t = a; a = b2; b2 = t;
        }
        if (tid == 0) s_off = atomicAdd(&g_gbase, a[511]);
        __syncthreads();
        int off = s_off;
        for (int i = tid; i < cnt; i += NTHR) {
            int v = a[i] - g_deg[base + i] + off;   // exclusive + global base
            g_start[base + i]  = v;
            g_cursor[base + i] = v;
        }
    }
    grid_barrier();

    // ---------------- Ph4: edge GEMM (steal x2) + CSR record scatter + e-stats
    {
        if (tid < D) { sA[tid] = 0.f; sB[tid] = 0.f; }
        __syncthreads();

        float ps0 = 0.f, ps1 = 0.f, ps2 = 0.f, ps3 = 0.f;
        float pq0 = 0.f, pq1 = 0.f, pq2 = 0.f, pq3 = 0.f;
        const float* wT = g_wT + 7 * D * D;
        float4 bb = *(const float4*)(B3b + c0);
        const int NSTRIP = NE / 8;     // 75000
        int sb = 0;
        if (lane == 0) sb = atomicAdd(&g_ctr4, 2);
        sb = __shfl_sync(FULL, sb, 0);
        while (sb < NSTRIP) {
            int nxt = 0;
            if (lane == 0) nxt = atomicAdd(&g_ctr4, 2);

            int send = sb + 2; if (send > NSTRIP) send = NSTRIP;
            for (int strip = sb; strip < send; strip++) {
                int row0 = strip * 8;
                unsigned long long acc[8][2];
#pragma unroll
                for (int j = 0; j < 8; j++) { acc[j][0] = 0ull; acc[j][1] = 0ull; }
                warp_gemm8(e + (size_t)row0 * D, wT, c0, acc);
#pragma unroll
                for (int j = 0; j < 8; j++) {
                    int er = row0 + j;
                    int s_ = src[er];
                    int t_ = dst[er];
                    float4 g1 = *(const float4*)(g_b1h + (size_t)s_ * D + c0);
                    float4 g2 = *(const float4*)(g_b2h + (size_t)t_ * D + c0);
                    float2 lo = upk2(acc[j][0]);
                    float2 hi = upk2(acc[j][1]);
                    float4 r;
                    r.x = lo.x + g1.x + g2.x + bb.x;
                    r.y = lo.y + g1.y + g2.y + bb.y;
                    r.z = hi.x + g1.z + g2.z + bb.z;
                    r.w = hi.y + g1.w + g2.w + bb.w;
                    *(uint2*)(g_hat16 + (size_t)er * D + c0) = pack_h4(r);  // fp16, sequential
                    if (lane == 0) {
                        int pos = atomicAdd(&g_cursor[t_], 1);
                        g_rec[pos] = make_int2(s_, er);                      // 8B scatter
                    }
                    ps0 += r.x; pq0 += r.x * r.x;
                    ps1 += r.y; pq1 += r.y * r.y;
                    ps2 += r.z; pq2 += r.z * r.z;
                    ps3 += r.w; pq3 += r.w * r.w;
                }
            }
            sb = __shfl_sync(FULL, nxt, 0);
        }
        atomicAdd(&sA[c0 + 0], ps0); atomicAdd(&sB[c0 + 0], pq0);
        atomicAdd(&sA[c0 + 1], ps1); atomicAdd(&sB[c0 + 1], pq1);
        atomicAdd(&sA[c0 + 2], ps2); atomicAdd(&sB[c0 + 2], pq2);
        atomicAdd(&sA[c0 + 3], ps3); atomicAdd(&sB[c0 + 3], pq3);
        __syncthreads();
        if (tid < D) {
            atomicAdd(&g_stats[tid], sA[tid]);
            atomicAdd(&g_stats[D + tid], sB[tid]);
        }
    }
    grid_barrier();

    // ---------------- Ph5: aggregation + fused e_final (steal, shfl recs) -----
    {
        if (tid < D) {
            float me  = g_stats[tid] * (1.0f / NE);
            float ve  = g_stats[D + tid] * (1.0f / NE) - me * me;
            float sce = bn_e_g[tid] * rsqrtf(ve + EPS_BN);
            s_ss[tid]     = sce;
            s_ss[D + tid] = bn_e_b[tid] - me * sce;
            sA[tid] = 0.f; sB[tid] = 0.f;
        }
        __syncthreads();
        const float4 sce = *(const float4*)(s_ss + c0);
        const float4 she = *(const float4*)(s_ss + D + c0);

        float ps0 = 0.f, ps1 = 0.f, ps2 = 0.f, ps3 = 0.f;
        float pq0 = 0.f, pq1 = 0.f, pq2 = 0.f, pq3 = 0.f;

        for (;;) {
            int nbase = 0;
            if (lane == 0) nbase = atomicAdd(&g_ctr5, 4);
            nbase = __shfl_sync(FULL, nbase, 0);
            if (nbase >= NN) break;
            int nend = nbase + 4; if (nend > NN) nend = NN;

            for (int n = nbase; n < nend; n++) {
                int st = g_start[n];
                int dg = g_deg[n];
                float4 ss = make_float4(0.f, 0.f, 0.f, 0.f);
                float4 ah = make_float4(0.f, 0.f, 0.f, 0.f);
                float4 ap = make_float4(0.f, 0.f, 0.f, 0.f);

                int done = 0;
                while (done < dg) {
                    int m = dg - done; if (m > 32) m = 32;
                    int2 rr = make_int2(0, 0);
                    if (lane < m) rr = g_rec[st + done + lane];
                    int j = 0;
                    for (; j + 2 <= m; j += 2) {
                        int sa = __shfl_sync(FULL, rr.x, j);
                        int ea = __shfl_sync(FULL, rr.y, j);
                        int sb_ = __shfl_sync(FULL, rr.x, j + 1);
                        int eb = __shfl_sync(FULL, rr.y, j + 1);
                        const float4 hva = unpack_h4(*(const uint2*)(g_hat16 + (size_t)ea * D + c0));
                        const float4 hvb = unpack_h4(*(const uint2*)(g_hat16 + (size_t)eb * D + c0));
                        const float4 vva = unpack_h4(*(const uint2*)(g_v16 + (size_t)sa * D + c0));
                        const float4 vvb = unpack_h4(*(const uint2*)(g_v16 + (size_t)sb_ * D + c0));
                        const float4 cpa = unpack_h4(*(const uint2*)(g_c2p16 + (size_t)sa * D + c0));
                        const float4 cpb = unpack_h4(*(const uint2*)(g_c2p16 + (size_t)sb_ * D + c0));
                        const float4 eva = *(const float4*)(e + (size_t)ea * D + c0);
                        const float4 evb = *(const float4*)(e + (size_t)eb * D + c0);
                        float a0 = sigf(hva.x), a1 = sigf(hva.y), a2 = sigf(hva.z), a3 = sigf(hva.w);
                        float b0 = sigf(hvb.x), b1 = sigf(hvb.y), b2 = sigf(hvb.z), b3 = sigf(hvb.w);
                        ss.x += a0 + b0; ss.y += a1 + b1; ss.z += a2 + b2; ss.w += a3 + b3;
                        ah.x = fmaf(a0, vva.x, fmaf(b0, vvb.x, ah.x));
                        ah.y = fmaf(a1, vva.y, fmaf(b1, vvb.y, ah.y));
                        ah.z = fmaf(a2, vva.z, fmaf(b2, vvb.z, ah.z));
                        ah.w = fmaf(a3, vva.w, fmaf(b3, vvb.w, ah.w));
                        ap.x = fmaf(a0, cpa.x, fmaf(b0, cpb.x, ap.x));
                        ap.y = fmaf(a1, cpa.y, fmaf(b1, cpb.y, ap.y));
                        ap.z = fmaf(a2, cpa.z, fmaf(b2, cpb.z, ap.z));
                        ap.w = fmaf(a3, cpa.w, fmaf(b3, cpb.w, ap.w));
                        float4 eo;
                        eo.x = eva.x + fmaxf(fmaf(hva.x, sce.x, she.x), 0.f);
                        eo.y = eva.y + fmaxf(fmaf(hva.y, sce.y, she.y), 0.f);
                        eo.z = eva.z + fmaxf(fmaf(hva.z, sce.z, she.z), 0.f);
                        eo.w = eva.w + fmaxf(fmaf(hva.w, sce.w, she.w), 0.f);
                        *(float4*)(ehat + (size_t)ea * D + c0) = eo;
                        eo.x = evb.x + fmaxf(fmaf(hvb.x, sce.x, she.x), 0.f);
                        eo.y = evb.y + fmaxf(fmaf(hvb.y, sce.y, she.y), 0.f);
                        eo.z = evb.z + fmaxf(fmaf(hvb.z, sce.z, she.z), 0.f);
                        eo.w = evb.w + fmaxf(fmaf(hvb.w, sce.w, she.w), 0.f);
                        *(float4*)(ehat + (size_t)eb * D + c0) = eo;
                    }
                    if (j < m) {
                        int sa = __shfl_sync(FULL, rr.x, j);
                        int ea = __shfl_sync(FULL, rr.y, j);
                        const float4 hv = unpack_h4(*(const uint2*)(g_hat16 + (size_t)ea * D + c0));
                        const float4 vv = unpack_h4(*(const uint2*)(g_v16 + (size_t)sa * D + c0));
                        const float4 cp = unpack_h4(*(const uint2*)(g_c2p16 + (size_t)sa * D + c0));
                        const float4 ev = *(const float4*)(e + (size_t)ea * D + c0);
                        float s0 = sigf(hv.x), s1 = sigf(hv.y), s2 = sigf(hv.z), s3 = sigf(hv.w);
                        ss.x += s0; ss.y += s1; ss.z += s2; ss.w += s3;
                        ah.x = fmaf(s0, vv.x, ah.x);
                        ah.y = fmaf(s1, vv.y, ah.y);
                        ah.z = fmaf(s2, vv.z, ah.z);
                        ah.w = fmaf(s3, vv.w, ah.w);
                        ap.x = fmaf(s0, cp.x, ap.x);
                        ap.y = fmaf(s1, cp.y, ap.y);
                        ap.z = fmaf(s2, cp.z, ap.z);
                        ap.w = fmaf(s3, cp.w, ap.w);
                        float4 eo;
                        eo.x = ev.x + fmaxf(fmaf(hv.x, sce.x, she.x), 0.f);
                        eo.y = ev.y + fmaxf(fmaf(hv.y, sce.y, she.y), 0.f);
                        eo.z = ev.z + fmaxf(fmaf(hv.z, sce.z, she.z), 0.f);
                        eo.w = ev.w + fmaxf(fmaf(hv.w, sce.w, she.w), 0.f);
                        *(float4*)(ehat + (size_t)ea * D + c0) = eo;
                    }
                    done += m;
                }
                float i0 = __fdividef(1.0f, ss.x + EPS_ETA);
                float i1 = __fdividef(1.0f, ss.y + EPS_ETA);
                float i2 = __fdividef(1.0f, ss.z + EPS_ETA);
                float i3 = __fdividef(1.0f, ss.w + EPS_ETA);

                size_t off = (size_t)n * D + c0;
                float4 a1v = *(const float4*)(g_a1h + off);
                float4 hn = make_float4(fmaf(ah.x, i0, a1v.x), fmaf(ah.y, i1, a1v.y),
                                        fmaf(ah.z, i2, a1v.z), fmaf(ah.w, i3, a1v.w));
                *(float4*)(g_agg_h + off) = hn;
                ps0 += hn.x; pq0 += hn.x * hn.x;
                ps1 += hn.y; pq1 += hn.y * hn.y;
                ps2 += hn.z; pq2 += hn.z * hn.z;
                ps3 += hn.w; pq3 += hn.w * hn.w;

                float4 c1 = *(const float4*)(g_c1p + off);
                float4 pv = *(const float4*)(p + off);
                float4 po;
                po.x = pv.x + tanh_fast(fmaf(ap.x, i0, c1.x));
                po.y = pv.y + tanh_fast(fmaf(ap.y, i1, c1.y));
                po.z = pv.z + tanh_fast(fmaf(ap.z, i2, c1.z));
                po.w = pv.w + tanh_fast(fmaf(ap.w, i3, c1.w));
                *(float4*)(p_out + off) = po;
            }
        }
        atomicAdd(&sA[c0 + 0], ps0); atomicAdd(&sB[c0 + 0], pq0);
        atomicAdd(&sA[c0 + 1], ps1); atomicAdd(&sB[c0 + 1], pq1);
        atomicAdd(&sA[c0 + 2], ps2); atomicAdd(&sB[c0 + 2], pq2);
        atomicAdd(&sA[c0 + 3], ps3); atomicAdd(&sB[c0 + 3], pq3);
        __syncthreads();
        if (tid < D) {
            atomicAdd(&g_stats[2 * D + tid], sA[tid]);
            atomicAdd(&g_stats[3 * D + tid], sB[tid]);
        }
    }
    grid_barrier();

    // ---------------- Ph6: h BN + h_out stream ----------------
    {
        if (tid < D) {
            float mh  = g_stats[2 * D + tid] * (1.0f / NN);
            float vh  = g_stats[3 * D + tid] * (1.0f / NN) - mh * mh;
            float sch = bn_h_g[tid] * rsqrtf(vh + EPS_BN);
            s_ss[tid]     = sch;
            s_ss[D + tid] = bn_h_b[tid] - mh * sch;
        }
        __syncthreads();

        for (int i = gtid; i < NN * 32; i += gstr) {
            int c = (i & 31) * 4;
            float4 sc = *(float4*)(s_ss + c);
            float4 sh = *(float4*)(s_ss + D + c);
            float4 hn = ((const float4*)g_agg_h)[i];
            float4 hv = ((const float4*)h)[i];
            float4 o;
            o.x = hv.x + fmaxf(fmaf(hn.x, sc.x, sh.x), 0.f);
            o.y = hv.y + fmaxf(fmaf(hn.y, sc.y, sh.y), 0.f);
            o.z = hv.z + fmaxf(fmaf(hn.z, sc.z, sh.z), 0.f);
            o.w = hv.w + fmaxf(fmaf(hn.w, sc.w, sh.w), 0.f);
            ((float4*)h_out)[i] = o;
        }
    }
}

// ---------------- launch -------------------------------------------------------
extern "C" void kernel_launch(void* const* d_in, const int* in_sizes, int n_in,
                              void* d_out, int out_size)
{
    const float* h   = (const float*)d_in[0];
    const float* e   = (const float*)d_in[1];
    const float* p   = (const float*)d_in[2];
    const int*   src = (const int*)d_in[3];
    const int*   dst = (const int*)d_in[4];
    const float* A1w = (const float*)d_in[5];
    const float* A1b = (const float*)d_in[6];
    const float* A2w = (const float*)d_in[7];
    const float* A2b = (const float*)d_in[8];
    const float* B1w = (const float*)d_in[9];
    const float* B1b = (const float*)d_in[10];
    const float* B2w = (const float*)d_in[11];
    const float* B2b = (const float*)d_in[12];
    const float* B3w = (const float*)d_in[13];
    const float* B3b = (const float*)d_in[14];
    const float* C1w = (const float*)d_in[15];
    const float* C1b = (const float*)d_in[16];
    const float* C2w = (const float*)d_in[17];
    const float* C2b = (const float*)d_in[18];
    const float* bn_h_g = (const float*)d_in[19];
    const float* bn_h_b = (const float*)d_in[20];
    const float* bn_e_g = (const float*)d_in[21];
    const float* bn_e_b = (const float*)d_in[22];

    float* out   = (float*)d_out;
    float* h_out = out;
    float* ehat  = out + (size_t)NN * D;
    float* p_out = out + (size_t)(NN + NE) * D;

    fused_gcn<<<NBLK, NTHR>>>(h, e, p, src, dst,
                              A1w, A1b, A2w, A2b,
                              B1w, B1b, B2w, B2b, B3w, B3b,
                              C1w, C1b, C2w, C2b,
                              bn_h_g, bn_h_b, bn_e_g, bn_e_b,
                              h_out, ehat, p_out);

    (void)in_sizes; (void)n_in; (void)out_size;
}

// round 17
// speedup vs baseline: 1.2807x; 1.0080x over previous
#include <cuda_runtime.h>
#include <cuda_fp16.h>
#include <math.h>

#define D       128
#define NN      50000
#define NE      600000
#define EPS_BN  1e-5f
#define EPS_ETA 1e-6f
#define NBLK    148
#define NTHR    1024
#define NWARP   32
#define CHUNK   338          // ceil(NN / NBLK)

// ---------------- device-global scratch (no allocations allowed) -------------
__device__ float  g_wT[8 * D * D];    // transposed weights: [k*D + c]
__device__ __half g_b1h16[NN * D];    // B1 h in fp16
__device__ __half g_b2h16[NN * D];    // B2 h in fp16
__device__ float  g_a1h[NN * D];
__device__ __half g_v16[NN * D];      // A2([h;p]) in fp16
__device__ float  g_c1p[NN * D];
__device__ __half g_c2p16[NN * D];    // C2 p in fp16
__device__ __half g_hat16[NE * D];    // raw hat_eta in fp16
__device__ float  g_agg_h[NN * D];    // h_new
__device__ int2   g_rec[NE];          // (src, eid) in dst-sorted (CSR) order
__device__ float  g_stats[4 * D];     // e_sum, e_sq, h_sum, h_sq
__device__ int    g_deg[NN];
__device__ int    g_start[NN];
__device__ int    g_cursor[NN];
__device__ int    g_gbase = 0;
__device__ int    g_ctr1 = 0;         // work-steal counters
__device__ int    g_ctr4 = 0;
__device__ int    g_ctr5 = 0;
__device__ int            g_bar_count = 0;
__device__ volatile int   g_bar_gen   = 0;

__device__ __forceinline__ float sigf(float x) {
    return __fdividef(1.0f, 1.0f + __expf(-x));
}
__device__ __forceinline__ float tanh_fast(float x) {
    x = fminf(15.0f, fmaxf(-15.0f, x));
    float t = __expf(2.0f * x);
    return __fdividef(t - 1.0f, t + 1.0f);
}

// fp16x4 pack/unpack via uint2
__device__ __forceinline__ uint2 pack_h4(float4 r) {
    __half2 a = __floats2half2_rn(r.x, r.y);
    __half2 b = __floats2half2_rn(r.z, r.w);
    uint2 u;
    u.x = *reinterpret_cast<unsigned*>(&a);
    u.y = *reinterpret_cast<unsigned*>(&b);
    return u;
}
__device__ __forceinline__ float4 unpack_h4(uint2 u) {
    __half2 a = *reinterpret_cast<__half2*>(&u.x);
    __half2 b = *reinterpret_cast<__half2*>(&u.y);
    float2 fa = __half22float2(a);
    float2 fb = __half22float2(b);
    return make_float4(fa.x, fa.y, fb.x, fb.y);
}

// ---------------- software grid barrier (all NBLK blocks co-resident) --------
__device__ __forceinline__ void grid_barrier()
{
    __syncthreads();
    if (threadIdx.x == 0) {
        int gen = g_bar_gen;
        __threadfence();
        if (atomicAdd(&g_bar_count, 1) == NBLK - 1) {
            g_bar_count = 0;
            __threadfence();
            g_bar_gen = gen + 1;
        } else {
            while (g_bar_gen == gen) { __nanosleep(64); }
        }
        __threadfence();
    }
    __syncthreads();
}

// ---------------- packed f32x2 helpers (sm_103a) -------------------------------
__device__ __forceinline__ unsigned long long pk2(float a, float b) {
    unsigned long long r;
    asm("mov.b64 %0, {%1, %2};" : "=l"(r) : "f"(a), "f"(b));
    return r;
}
__device__ __forceinline__ float2 upk2(unsigned long long v) {
    float2 r;
    asm("mov.b64 {%0, %1}, %2;" : "=f"(r.x), "=f"(r.y) : "l"(v));
    return r;
}
__device__ __forceinline__ unsigned long long ffma2(
    unsigned long long a, unsigned long long b, unsigned long long c) {
    unsigned long long d;
    asm("fma.rn.f32x2 %0, %1, %2, %3;" : "=l"(d) : "l"(a), "l"(b), "l"(c));
    return d;
}

// ---------------- sync-free warp GEMM: 8 rows x 128 cols, K=128 ----------------
__device__ __forceinline__ void warp_gemm8(
    const float* __restrict__ Xr,
    const float* __restrict__ wT,
    int c0, unsigned long long acc[8][2])
{
    for (int k = 0; k < D; k += 4) {
        ulonglong2 w0 = *(const ulonglong2*)(wT + (size_t)(k + 0) * D + c0);
        ulonglong2 w1 = *(const ulonglong2*)(wT + (size_t)(k + 1) * D + c0);
        ulonglong2 w2 = *(const ulonglong2*)(wT + (size_t)(k + 2) * D + c0);
        ulonglong2 w3 = *(const ulonglong2*)(wT + (size_t)(k + 3) * D + c0);
#pragma unroll
        for (int j = 0; j < 8; j++) {
            float4 xv = *(const float4*)(Xr + (size_t)j * D + k);
            unsigned long long b;
            b = pk2(xv.x, xv.x);
            acc[j][0] = ffma2(b, w0.x, acc[j][0]);
            acc[j][1] = ffma2(b, w0.y, acc[j][1]);
            b = pk2(xv.y, xv.y);
            acc[j][0] = ffma2(b, w1.x, acc[j][0]);
            acc[j][1] = ffma2(b, w1.y, acc[j][1]);
            b = pk2(xv.z, xv.z);
            acc[j][0] = ffma2(b, w2.x, acc[j][0]);
            acc[j][1] = ffma2(b, w2.y, acc[j][1]);
            b = pk2(xv.w, xv.w);
            acc[j][0] = ffma2(b, w3.x, acc[j][0]);
            acc[j][1] = ffma2(b, w3.y, acc[j][1]);
        }
    }
}

// =============================================================================
// Single fused persistent kernel. grid = 148 x 1024.
// =============================================================================
__global__ void __launch_bounds__(NTHR) fused_gcn(
    const float* __restrict__ h, const float* __restrict__ e, const float* __restrict__ p,
    const int* __restrict__ src, const int* __restrict__ dst,
    const float* __restrict__ A1w, const float* __restrict__ A1b,
    const float* __restrict__ A2w, const float* __restrict__ A2b,
    const float* __restrict__ B1w, const float* __restrict__ B1b,
    const float* __restrict__ B2w, const float* __restrict__ B2b,
    const float* __restrict__ B3w, const float* __restrict__ B3b,
    const float* __restrict__ C1w, const float* __restrict__ C1b,
    const float* __restrict__ C2w, const float* __restrict__ C2b,
    const float* __restrict__ bn_h_g, const float* __restrict__ bn_h_b,
    const float* __restrict__ bn_e_g, const float* __restrict__ bn_e_b,
    float* __restrict__ h_out, float* __restrict__ ehat, float* __restrict__ p_out)
{
    __shared__ int   s_scan[512];
    __shared__ int   s_scan2[512];
    __shared__ float sA[D];
    __shared__ float sB[D];
    __shared__ float s_ss[2 * D];
    __shared__ int   s_off;

    const int tid  = threadIdx.x;
    const int lane = tid & 31;
    const int warp = tid >> 5;
    const int bid  = blockIdx.x;
    const int c0   = lane * 4;
    const int gtid = bid * NTHR + tid;
    const int gstr = NBLK * NTHR;          // 151552
    const unsigned FULL = 0xFFFFFFFFu;

    // ---------------- Ph0: zero deg/stats/counters + weight transpose ---------
    for (int i = gtid; i < NN; i += gstr) g_deg[i] = 0;
    if (gtid < 4 * D) g_stats[gtid] = 0.f;
    if (gtid == 0) { g_gbase = 0; g_ctr1 = 0; g_ctr4 = 0; g_ctr5 = 0; }
    for (int i = gtid; i < 8 * D * D; i += gstr) {
        int j   = i >> 14;
        int rem = i & 16383;
        int k   = rem >> 7;
        int c   = rem & 127;
        float v;
        if      (j == 0) v = B1w[c * D + k];
        else if (j == 1) v = B2w[c * D + k];
        else if (j == 2) v = A1w[c * D + k];
        else if (j == 3) v = C1w[c * D + k];
        else if (j == 4) v = C2w[c * D + k];
        else if (j == 5) v = A2w[c * 2 * D + k];
        else if (j == 6) v = A2w[c * 2 * D + D + k];
        else             v = B3w[c * D + k];
        g_wT[i] = v;
    }
    grid_barrier();

    // ---------------- Ph1: dst histogram + node GEMMs (work-stealing x2) ------
    for (int ei = gtid; ei < NE; ei += gstr) atomicAdd(&g_deg[dst[ei]], 1);
    {
        const int NSTRIP = NN / 8;     // 6250
        const int NJOB   = 6 * NSTRIP;
        int jb = 0;
        if (lane == 0) jb = atomicAdd(&g_ctr1, 2);
        jb = __shfl_sync(FULL, jb, 0);
        while (jb < NJOB) {
            int nxt = 0;
            if (lane == 0) nxt = atomicAdd(&g_ctr1, 2);

            int jend = jb + 2; if (jend > NJOB) jend = NJOB;
            for (int job = jb; job < jend; job++) {
                int jid   = job / NSTRIP;
                int strip = job - jid * NSTRIP;
                int row0  = strip * 8;
                unsigned long long acc[8][2];
#pragma unroll
                for (int j = 0; j < 8; j++) { acc[j][0] = 0ull; acc[j][1] = 0ull; }

                const float* bias;
                float* outp = nullptr;
                __half* outp16 = nullptr;
                if (jid == 0) {
                    warp_gemm8(h + (size_t)row0 * D, g_wT + 0 * D * D, c0, acc);
                    bias = B1b; outp16 = g_b1h16;
                } else if (jid == 1) {
                    warp_gemm8(h + (size_t)row0 * D, g_wT + 1 * D * D, c0, acc);
                    bias = B2b; outp16 = g_b2h16;
                } else if (jid == 2) {
                    warp_gemm8(h + (size_t)row0 * D, g_wT + 2 * D * D, c0, acc);
                    bias = A1b; outp = g_a1h;
                } else if (jid == 3) {
                    warp_gemm8(p + (size_t)row0 * D, g_wT + 3 * D * D, c0, acc);
                    bias = C1b; outp = g_c1p;
                } else if (jid == 4) {
                    warp_gemm8(p + (size_t)row0 * D, g_wT + 4 * D * D, c0, acc);
                    bias = C2b; outp16 = g_c2p16;
                } else {
                    warp_gemm8(h + (size_t)row0 * D, g_wT + 5 * D * D, c0, acc);
                    warp_gemm8(p + (size_t)row0 * D, g_wT + 6 * D * D, c0, acc);
                    bias = A2b; outp16 = g_v16;
                }
                float4 bb = *(const float4*)(bias + c0);
#pragma unroll
                for (int j = 0; j < 8; j++) {
                    float2 lo = upk2(acc[j][0]);
                    float2 hi = upk2(acc[j][1]);
                    float4 r = make_float4(lo.x + bb.x, lo.y + bb.y, hi.x + bb.z, hi.y + bb.w);
                    if (outp16) {
                        *(uint2*)(outp16 + (size_t)(row0 + j) * D + c0) = pack_h4(r);
                    } else {
                        *(float4*)(outp + (size_t)(row0 + j) * D + c0) = r;
                    }
                }
            }
            jb = __shfl_sync(FULL, nxt, 0);
        }
    }
    grid_barrier();

    // ---------------- Ph2: per-block scan + atomic global base ----------------
    {
        int base = bid * CHUNK;
        int cnt  = NN - base; if (cnt > CHUNK) cnt = CHUNK; if (cnt < 0) cnt = 0;
        for (int i = tid; i < 512; i += NTHR) s_scan[i] = (i < cnt) ? g_deg[base + i] : 0;
        __syncthreads();
        int* a  = s_scan;
        int* b2 = s_scan2;
        for (int d0 = 1; d0 < 512; d0 <<= 1) {
            for (int i = tid; i < 512; i += NTHR) {
                int v = a[i];
                if (i >= d0) v += a[i - d0];
                b2[i] = v;
            }
            __syncthreads();
            int* t = a; a = b2; b2 = t;
        }
        if (tid == 0) s_off = atomicAdd(&g_gbase, a[511]);
        __syncthreads();
        int off = s_off;
        for (int i = tid; i < cnt; i += NTHR) {
            int v = a[i] - g_deg[base + i] + off;   // exclusive + global base
            g_start[base + i]  = v;
            g_cursor[base + i] = v;
        }
    }
    grid_barrier();

    // ---------------- Ph4: edge GEMM (steal x2) + CSR record scatter + e-stats
    {
        if (tid < D) { sA[tid] = 0.f; sB[tid] = 0.f; }
        __syncthreads();

        float ps0 = 0.f, ps1 = 0.f, ps2 = 0.f, ps3 = 0.f;
        float pq0 = 0.f, pq1 = 0.f, pq2 = 0.f, pq3 = 0.f;
        const float* wT = g_wT + 7 * D * D;
        float4 bb = *(const float4*)(B3b + c0);
        const int NSTRIP = NE / 8;     // 75000
        int sb = 0;
        if (lane == 0) sb = atomicAdd(&g_ctr4, 2);
        sb = __shfl_sync(FULL, sb, 0);
        while (sb < NSTRIP) {
            int nxt = 0;
            if (lane == 0) nxt = atomicAdd(&g_ctr4, 2);

            int send = sb + 2; if (send > NSTRIP) send = NSTRIP;
            for (int strip = sb; strip < send; strip++) {
                int row0 = strip * 8;
                unsigned long long acc[8][2];
#pragma unroll
                for (int j = 0; j < 8; j++) { acc[j][0] = 0ull; acc[j][1] = 0ull; }
                warp_gemm8(e + (size_t)row0 * D, wT, c0, acc);
#pragma unroll
                for (int j = 0; j < 8; j++) {
                    int er = row0 + j;
                    int s_ = src[er];
                    int t_ = dst[er];
                    float4 g1 = unpack_h4(*(const uint2*)(g_b1h16 + (size_t)s_ * D + c0));
                    float4 g2 = unpack_h4(*(const uint2*)(g_b2h16 + (size_t)t_ * D + c0));
                    float2 lo = upk2(acc[j][0]);
                    float2 hi = upk2(acc[j][1]);
                    float4 r;
                    r.x = lo.x + g1.x + g2.x + bb.x;
                    r.y = lo.y + g1.y + g2.y + bb.y;
                    r.z = hi.x + g1.z + g2.z + bb.z;
                    r.w = hi.y + g1.w + g2.w + bb.w;
                    *(uint2*)(g_hat16 + (size_t)er * D + c0) = pack_h4(r);  // fp16, sequential
                    if (lane == 0) {
                        int pos = atomicAdd(&g_cursor[t_], 1);
                        g_rec[pos] = make_int2(s_, er);                      // 8B scatter
                    }
                    ps0 += r.x; pq0 += r.x * r.x;
                    ps1 += r.y; pq1 += r.y * r.y;
                    ps2 += r.z; pq2 += r.z * r.z;
                    ps3 += r.w; pq3 += r.w * r.w;
                }
            }
            sb = __shfl_sync(FULL, nxt, 0);
        }
        atomicAdd(&sA[c0 + 0], ps0); atomicAdd(&sB[c0 + 0], pq0);
        atomicAdd(&sA[c0 + 1], ps1); atomicAdd(&sB[c0 + 1], pq1);
        atomicAdd(&sA[c0 + 2], ps2); atomicAdd(&sB[c0 + 2], pq2);
        atomicAdd(&sA[c0 + 3], ps3); atomicAdd(&sB[c0 + 3], pq3);
        __syncthreads();
        if (tid < D) {
            atomicAdd(&g_stats[tid], sA[tid]);
            atomicAdd(&g_stats[D + tid], sB[tid]);
        }
    }
    grid_barrier();

    // ---------------- Ph5: aggregation + fused e_final (steal, shfl recs) -----
    {
        if (tid < D) {
            float me  = g_stats[tid] * (1.0f / NE);
            float ve  = g_stats[D + tid] * (1.0f / NE) - me * me;
            float sce = bn_e_g[tid] * rsqrtf(ve + EPS_BN);
            s_ss[tid]     = sce;
            s_ss[D + tid] = bn_e_b[tid] - me * sce;
            sA[tid] = 0.f; sB[tid] = 0.f;
        }
        __syncthreads();
        const float4 sce = *(const float4*)(s_ss + c0);
        const float4 she = *(const float4*)(s_ss + D + c0);

        float ps0 = 0.f, ps1 = 0.f, ps2 = 0.f, ps3 = 0.f;
        float pq0 = 0.f, pq1 = 0.f, pq2 = 0.f, pq3 = 0.f;

        for (;;) {
            int nbase = 0;
            if (lane == 0) nbase = atomicAdd(&g_ctr5, 4);
            nbase = __shfl_sync(FULL, nbase, 0);
            if (nbase >= NN) break;
            int nend = nbase + 4; if (nend > NN) nend = NN;

            for (int n = nbase; n < nend; n++) {
                int st = g_start[n];
                int dg = g_deg[n];
                float4 ss = make_float4(0.f, 0.f, 0.f, 0.f);
                float4 ah = make_float4(0.f, 0.f, 0.f, 0.f);
                float4 ap = make_float4(0.f, 0.f, 0.f, 0.f);

                int done = 0;
                while (done < dg) {
                    int m = dg - done; if (m > 32) m = 32;
                    int2 rr = make_int2(0, 0);
                    if (lane < m) rr = g_rec[st + done + lane];
                    int j = 0;
                    for (; j + 2 <= m; j += 2) {
                        int sa = __shfl_sync(FULL, rr.x, j);
                        int ea = __shfl_sync(FULL, rr.y, j);
                        int sb_ = __shfl_sync(FULL, rr.x, j + 1);
                        int eb = __shfl_sync(FULL, rr.y, j + 1);
                        const float4 hva = unpack_h4(*(const uint2*)(g_hat16 + (size_t)ea * D + c0));
                        const float4 hvb = unpack_h4(*(const uint2*)(g_hat16 + (size_t)eb * D + c0));
                        const float4 vva = unpack_h4(*(const uint2*)(g_v16 + (size_t)sa * D + c0));
                        const float4 vvb = unpack_h4(*(const uint2*)(g_v16 + (size_t)sb_ * D + c0));
                        const float4 cpa = unpack_h4(*(const uint2*)(g_c2p16 + (size_t)sa * D + c0));
                        const float4 cpb = unpack_h4(*(const uint2*)(g_c2p16 + (size_t)sb_ * D + c0));
                        const float4 eva = *(const float4*)(e + (size_t)ea * D + c0);
                        const float4 evb = *(const float4*)(e + (size_t)eb * D + c0);
                        float a0 = sigf(hva.x), a1 = sigf(hva.y), a2 = sigf(hva.z), a3 = sigf(hva.w);
                        float b0 = sigf(hvb.x), b1 = sigf(hvb.y), b2 = sigf(hvb.z), b3 = sigf(hvb.w);
                        ss.x += a0 + b0; ss.y += a1 + b1; ss.z += a2 + b2; ss.w += a3 + b3;
                        ah.x = fmaf(a0, vva.x, fmaf(b0, vvb.x, ah.x));
                        ah.y = fmaf(a1, vva.y, fmaf(b1, vvb.y, ah.y));
                        ah.z = fmaf(a2, vva.z, fmaf(b2, vvb.z, ah.z));
                        ah.w = fmaf(a3, vva.w, fmaf(b3, vvb.w, ah.w));
                        ap.x = fmaf(a0, cpa.x, fmaf(b0, cpb.x, ap.x));
                        ap.y = fmaf(a1, cpa.y, fmaf(b1, cpb.y, ap.y));
                        ap.z = fmaf(a2, cpa.z, fmaf(b2, cpb.z, ap.z));
                        ap.w = fmaf(a3, cpa.w, fmaf(b3, cpb.w, ap.w));
                        float4 eo;
                        eo.x = eva.x + fmaxf(fmaf(hva.x, sce.x, she.x), 0.f);
                        eo.y = eva.y + fmaxf(fmaf(hva.y, sce.y, she.y), 0.f);
                        eo.z = eva.z + fmaxf(fmaf(hva.z, sce.z, she.z), 0.f);
                        eo.w = eva.w + fmaxf(fmaf(hva.w, sce.w, she.w), 0.f);
                        *(float4*)(ehat + (size_t)ea * D + c0) = eo;
                        eo.x = evb.x + fmaxf(fmaf(hvb.x, sce.x, she.x), 0.f);
                        eo.y = evb.y + fmaxf(fmaf(hvb.y, sce.y, she.y), 0.f);
                        eo.z = evb.z + fmaxf(fmaf(hvb.z, sce.z, she.z), 0.f);
                        eo.w = evb.w + fmaxf(fmaf(hvb.w, sce.w, she.w), 0.f);
                        *(float4*)(ehat + (size_t)eb * D + c0) = eo;
                    }
                    if (j < m) {
                        int sa = __shfl_sync(FULL, rr.x, j);
                        int ea = __shfl_sync(FULL, rr.y, j);
                        const float4 hv = unpack_h4(*(const uint2*)(g_hat16 + (size_t)ea * D + c0));
                        const float4 vv = unpack_h4(*(const uint2*)(g_v16 + (size_t)sa * D + c0));
                        const float4 cp = unpack_h4(*(const uint2*)(g_c2p16 + (size_t)sa * D + c0));
                        const float4 ev = *(const float4*)(e + (size_t)ea * D + c0);
                        float s0 = sigf(hv.x), s1 = sigf(hv.y), s2 = sigf(hv.z), s3 = sigf(hv.w);
                        ss.x += s0; ss.y += s1; ss.z += s2; ss.w += s3;
                        ah.x = fmaf(s0, vv.x, ah.x);
                        ah.y = fmaf(s1, vv.y, ah.y);
                        ah.z = fmaf(s2, vv.z, ah.z);
                        ah.w = fmaf(s3, vv.w, ah.w);
                        ap.x = fmaf(s0, cp.x, ap.x);
                        ap.y = fmaf(s1, cp.y, ap.y);
                        ap.z = fmaf(s2, cp.z, ap.z);
                        ap.w = fmaf(s3, cp.w, ap.w);
                        float4 eo;
                        eo.x = ev.x + fmaxf(fmaf(hv.x, sce.x, she.x), 0.f);
                        eo.y = ev.y + fmaxf(fmaf(hv.y, sce.y, she.y), 0.f);
                        eo.z = ev.z + fmaxf(fmaf(hv.z, sce.z, she.z), 0.f);
                        eo.w = ev.w + fmaxf(fmaf(hv.w, sce.w, she.w), 0.f);
                        *(float4*)(ehat + (size_t)ea * D + c0) = eo;
                    }
                    done += m;
                }
                float i0 = __fdividef(1.0f, ss.x + EPS_ETA);
                float i1 = __fdividef(1.0f, ss.y + EPS_ETA);
                float i2 = __fdividef(1.0f, ss.z + EPS_ETA);
                float i3 = __fdividef(1.0f, ss.w + EPS_ETA);

                size_t off = (size_t)n * D + c0;
                float4 a1v = *(const float4*)(g_a1h + off);
                float4 hn = make_float4(fmaf(ah.x, i0, a1v.x), fmaf(ah.y, i1, a1v.y),
                                        fmaf(ah.z, i2, a1v.z), fmaf(ah.w, i3, a1v.w));
                *(float4*)(g_agg_h + off) = hn;
                ps0 += hn.x; pq0 += hn.x * hn.x;
                ps1 += hn.y; pq1 += hn.y * hn.y;
                ps2 += hn.z; pq2 += hn.z * hn.z;
                ps3 += hn.w; pq3 += hn.w * hn.w;

                float4 c1 = *(const float4*)(g_c1p + off);
                float4 pv = *(const float4*)(p + off);
                float4 po;
                po.x = pv.x + tanh_fast(fmaf(ap.x, i0, c1.x));
                po.y = pv.y + tanh_fast(fmaf(ap.y, i1, c1.y));
                po.z = pv.z + tanh_fast(fmaf(ap.z, i2, c1.z));
                po.w = pv.w + tanh_fast(fmaf(ap.w, i3, c1.w));
                *(float4*)(p_out + off) = po;
            }
        }
        atomicAdd(&sA[c0 + 0], ps0); atomicAdd(&sB[c0 + 0], pq0);
        atomicAdd(&sA[c0 + 1], ps1); atomicAdd(&sB[c0 + 1], pq1);
        atomicAdd(&sA[c0 + 2], ps2); atomicAdd(&sB[c0 + 2], pq2);
        atomicAdd(&sA[c0 + 3], ps3); atomicAdd(&sB[c0 + 3], pq3);
        __syncthreads();
        if (tid < D) {
            atomicAdd(&g_stats[2 * D + tid], sA[tid]);
            atomicAdd(&g_stats[3 * D + tid], sB[tid]);
        }
    }
    grid_barrier();

    // ---------------- Ph6: h BN + h_out stream ----------------
    {
        if (tid < D) {
            float mh  = g_stats[2 * D + tid] * (1.0f / NN);
            float vh  = g_stats[3 * D + tid] * (1.0f / NN) - mh * mh;
            float sch = bn_h_g[tid] * rsqrtf(vh + EPS_BN);
            s_ss[tid]     = sch;
            s_ss[D + tid] = bn_h_b[tid] - mh * sch;
        }
        __syncthreads();

        for (int i = gtid; i < NN * 32; i += gstr) {
            int c = (i & 31) * 4;
            float4 sc = *(float4*)(s_ss + c);
            float4 sh = *(float4*)(s_ss + D + c);
            float4 hn = ((const float4*)g_agg_h)[i];
            float4 hv = ((const float4*)h)[i];
            float4 o;
            o.x = hv.x + fmaxf(fmaf(hn.x, sc.x, sh.x), 0.f);
            o.y = hv.y + fmaxf(fmaf(hn.y, sc.y, sh.y), 0.f);
            o.z = hv.z + fmaxf(fmaf(hn.z, sc.z, sh.z), 0.f);
            o.w = hv.w + fmaxf(fmaf(hn.w, sc.w, sh.w), 0.f);
            ((float4*)h_out)[i] = o;
        }
    }
}

// ---------------- launch -------------------------------------------------------
extern "C" void kernel_launch(void* const* d_in, const int* in_sizes, int n_in,
                              void* d_out, int out_size)
{
    const float* h   = (const float*)d_in[0];
    const float* e   = (const float*)d_in[1];
    const float* p   = (const float*)d_in[2];
    const int*   src = (const int*)d_in[3];
    const int*   dst = (const int*)d_in[4];
    const float* A1w = (const float*)d_in[5];
    const float* A1b = (const float*)d_in[6];
    const float* A2w = (const float*)d_in[7];
    const float* A2b = (const float*)d_in[8];
    const float* B1w = (const float*)d_in[9];
    const float* B1b = (const float*)d_in[10];
    const float* B2w = (const float*)d_in[11];
    const float* B2b = (const float*)d_in[12];
    const float* B3w = (const float*)d_in[13];
    const float* B3b = (const float*)d_in[14];
    const float* C1w = (const float*)d_in[15];
    const float* C1b = (const float*)d_in[16];
    const float* C2w = (const float*)d_in[17];
    const float* C2b = (const float*)d_in[18];
    const float* bn_h_g = (const float*)d_in[19];
    const float* bn_h_b = (const float*)d_in[20];
    const float* bn_e_g = (const float*)d_in[21];
    const float* bn_e_b = (const float*)d_in[22];

    float* out   = (float*)d_out;
    float* h_out = out;
    float* ehat  = out + (size_t)NN * D;
    float* p_out = out + (size_t)(NN + NE) * D;

    fused_gcn<<<NBLK, NTHR>>>(h, e, p, src, dst,
                              A1w, A1b, A2w, A2b,
                              B1w, B1b, B2w, B2b, B3w, B3b,
                              C1w, C1b, C2w, C2b,
                              bn_h_g, bn_h_b, bn_e_g, bn_e_b,
                              h_out, ehat, p_out);

    (void)in_sizes; (void)n_in; (void)out_size;
}